// round 1
// baseline (speedup 1.0000x reference)
#include <cuda_runtime.h>
#include <cstdint>

// ---------------------------------------------------------------------------
// Problem constants (fixed by the reference)
// ---------------------------------------------------------------------------
constexpr int kB   = 8;
constexpr int kN   = 512;
constexpr int kE   = 65536;
constexpr int kNT  = kB * kN;      // 4096
constexpr int kDIN = 128;
constexpr int kDH  = 64;
constexpr int kR   = 32;           // R_IN == R_OUT == 32

// ---------------------------------------------------------------------------
// Scratch (single __device__ global; no allocations allowed)
// ---------------------------------------------------------------------------
constexpr size_t SZ_NTDH = (size_t)kNT * kDH;     // 262144
constexpr size_t SZ_NTR  = (size_t)kNT * kR;      // 131072
constexpr size_t SZ_S    = (size_t)kB * kN * kN;  // 2097152

constexpr size_t OFF_YS     = 0;
constexpr size_t OFF_YT     = OFF_YS     + SZ_NTDH;
constexpr size_t OFF_AGG64S = OFF_YT     + SZ_NTDH;
constexpr size_t OFF_AGG64T = OFF_AGG64S + SZ_NTDH;
constexpr size_t OFF_HS     = OFF_AGG64T + SZ_NTDH;
constexpr size_t OFF_HT     = OFF_HS     + SZ_NTDH;
constexpr size_t OFF_SHAT   = OFF_HT     + SZ_NTDH;
constexpr size_t OFF_SNORM  = OFF_SHAT   + SZ_S;
constexpr size_t OFF_TMPA   = OFF_SNORM  + SZ_S;
constexpr size_t OFF_TMPB   = OFF_TMPA   + SZ_NTR;
constexpr size_t OFF_AGG32  = OFF_TMPB   + SZ_NTR;
constexpr size_t OFF_RT     = OFF_AGG32  + SZ_NTR;
constexpr size_t OFF_AS     = OFF_RT     + SZ_NTR;       // 2 steps
constexpr size_t OFF_BT     = OFF_AS     + 2 * SZ_NTR;
constexpr size_t SCRATCH_TOTAL = OFF_BT + SZ_NTR;

__device__ float g_scratch[SCRATCH_TOTAL];

// ---------------------------------------------------------------------------
// Utility: zero a float buffer
// ---------------------------------------------------------------------------
__global__ void zero_kernel(float* __restrict__ p, int n) {
    int i = blockIdx.x * blockDim.x + threadIdx.x;
    if (i < n) p[i] = 0.f;
}

// ---------------------------------------------------------------------------
// Row-parallel small GEMM: out[row, j] = act( bias[j] + sum_k A[row,k]*W[k,j] (+ add[row,j]) )
// grid.x = NT/RPB rows-blocks, block = Nc threads
// ---------------------------------------------------------------------------
template<int K, int Nc, int RPB, bool RELU, bool HASBIAS, bool HASADD>
__global__ void rowgemm(const float* __restrict__ A, const float* __restrict__ W,
                        const float* __restrict__ bias, const float* __restrict__ add,
                        float* __restrict__ out)
{
    __shared__ float As[RPB][K];
    int row0 = blockIdx.x * RPB;
    int j = threadIdx.x;
    for (int i = j; i < RPB * K; i += Nc) As[i / K][i % K] = A[(size_t)row0 * K + i];
    __syncthreads();
    float acc[RPB];
    #pragma unroll
    for (int rr = 0; rr < RPB; rr++) acc[rr] = HASBIAS ? bias[j] : 0.f;
    #pragma unroll 4
    for (int k = 0; k < K; k++) {
        float w = W[k * Nc + j];
        #pragma unroll
        for (int rr = 0; rr < RPB; rr++) acc[rr] = fmaf(As[rr][k], w, acc[rr]);
    }
    #pragma unroll
    for (int rr = 0; rr < RPB; rr++) {
        float v = acc[rr];
        if (HASADD) v += add[(size_t)(row0 + rr) * Nc + j];
        if (RELU)   v = fmaxf(v, 0.f);
        out[(size_t)(row0 + rr) * Nc + j] = v;
    }
}

// ---------------------------------------------------------------------------
// Edge scatter: agg[dst[e], :] += y[src[e], :] * ea[e]   (F = 64 or 32)
// One thread handles one (edge, 4-float chunk); vector reduction to L2.
// ---------------------------------------------------------------------------
template<int F>
__global__ void scatter_kernel(const float* __restrict__ y, const int* __restrict__ src,
                               const int* __restrict__ dst, const float* __restrict__ ea,
                               float* __restrict__ agg)
{
    constexpr int C = F / 4;
    int tid = blockIdx.x * blockDim.x + threadIdx.x;
    int e = tid / C;
    int c = tid % C;
    if (e >= kE) return;
    int s = src[e];
    int d = dst[e];
    float w = ea[e];
    float4 v = *reinterpret_cast<const float4*>(y + (size_t)s * F + c * 4);
    float* p = agg + (size_t)d * F + c * 4;
    asm volatile("red.global.add.v4.f32 [%0], {%1,%2,%3,%4};"
                 :: "l"(p), "f"(v.x * w), "f"(v.y * w), "f"(v.z * w), "f"(v.w * w)
                 : "memory");
}

// ---------------------------------------------------------------------------
// S_hat0[b] = h_s[b] @ h_t[b]^T     (512x512x64 per batch)
// grid (t_tiles=8, s_tiles=8, b=8), block 256, 64x64 tile, 4x4 micro-tile
// ---------------------------------------------------------------------------
__global__ void gemm_nt_kernel(const float* __restrict__ hs, const float* __restrict__ ht,
                               float* __restrict__ out)
{
    __shared__ float As[64][65];
    __shared__ float Bs[64][65];
    int b = blockIdx.z, s0 = blockIdx.y * 64, t0 = blockIdx.x * 64;
    const float* Ab = hs + ((size_t)b * kN + s0) * kDH;
    const float* Bb = ht + ((size_t)b * kN + t0) * kDH;
    int tid = threadIdx.x;
    for (int i = tid; i < 64 * 64; i += 256) {
        As[i >> 6][i & 63] = Ab[i];
        Bs[i >> 6][i & 63] = Bb[i];
    }
    __syncthreads();
    int tx = tid & 15, ty = tid >> 4;
    float acc[4][4];
    #pragma unroll
    for (int i = 0; i < 4; i++)
        #pragma unroll
        for (int j = 0; j < 4; j++) acc[i][j] = 0.f;
    #pragma unroll 8
    for (int k = 0; k < 64; k++) {
        float a[4], c[4];
        #pragma unroll
        for (int i = 0; i < 4; i++) a[i] = As[ty + i * 16][k];
        #pragma unroll
        for (int j = 0; j < 4; j++) c[j] = Bs[tx + j * 16][k];
        #pragma unroll
        for (int i = 0; i < 4; i++)
            #pragma unroll
            for (int j = 0; j < 4; j++) acc[i][j] = fmaf(a[i], c[j], acc[i][j]);
    }
    float* Ob = out + ((size_t)b * kN + s0) * kN + t0;
    #pragma unroll
    for (int i = 0; i < 4; i++)
        #pragma unroll
        for (int j = 0; j < 4; j++)
            Ob[(size_t)(ty + i * 16) * kN + tx + j * 16] = acc[i][j];
}

// ---------------------------------------------------------------------------
// Row softmax over last dim (512), dest may be d_out or scratch. S_hat unchanged.
// grid = 4096 rows, block 128, float4 per thread
// ---------------------------------------------------------------------------
__global__ void softmax_kernel(const float* __restrict__ shat, float* __restrict__ dest)
{
    __shared__ float redm[4];
    __shared__ float reds[4];
    int row = blockIdx.x;
    int tid = threadIdx.x;
    const float4* in = reinterpret_cast<const float4*>(shat + (size_t)row * kN);
    float4 v = in[tid];
    float m = fmaxf(fmaxf(v.x, v.y), fmaxf(v.z, v.w));
    #pragma unroll
    for (int o = 16; o > 0; o >>= 1) m = fmaxf(m, __shfl_xor_sync(0xffffffffu, m, o));
    if ((tid & 31) == 0) redm[tid >> 5] = m;
    __syncthreads();
    m = fmaxf(fmaxf(redm[0], redm[1]), fmaxf(redm[2], redm[3]));
    float4 e;
    e.x = __expf(v.x - m); e.y = __expf(v.y - m);
    e.z = __expf(v.z - m); e.w = __expf(v.w - m);
    float s = (e.x + e.y) + (e.z + e.w);
    #pragma unroll
    for (int o = 16; o > 0; o >>= 1) s += __shfl_xor_sync(0xffffffffu, s, o);
    if ((tid & 31) == 0) reds[tid >> 5] = s;
    __syncthreads();
    s = (reds[0] + reds[1]) + (reds[2] + reds[3]);
    float inv = 1.f / s;
    reinterpret_cast<float4*>(dest + (size_t)row * kN)[tid] =
        make_float4(e.x * inv, e.y * inv, e.z * inv, e.w * inv);
}

// ---------------------------------------------------------------------------
// r_t[b,t,r] = sum_s S[b,s,t] * r_s[b,s,r]    (S already normalized)
// grid (t_tiles=16, b=8), block 256 = (32 r) x (8 t-groups of 4)
// ---------------------------------------------------------------------------
__global__ void rt_gemm_kernel(const float* __restrict__ S, const float* __restrict__ rs,
                               float* __restrict__ rt)
{
    __shared__ float Ssm[8][32];
    __shared__ float Rsm[8][32];
    int b = blockIdx.y, t0 = blockIdx.x * 32;
    int tid = threadIdx.x;
    int r = tid & 31, tg = tid >> 5;
    const float* Sb = S + (size_t)b * kN * kN;
    const float* Rb = rs + (size_t)b * kN * kR;
    float acc[4] = {0.f, 0.f, 0.f, 0.f};
    for (int s0 = 0; s0 < kN; s0 += 8) {
        Ssm[tg][r] = Sb[(size_t)(s0 + tg) * kN + t0 + r];
        Rsm[tg][r] = Rb[(size_t)(s0 + tg) * kR + r];
        __syncthreads();
        #pragma unroll
        for (int q = 0; q < 8; q++) {
            float rv = Rsm[q][r];
            #pragma unroll
            for (int j = 0; j < 4; j++)
                acc[j] = fmaf(Ssm[q][tg * 4 + j], rv, acc[j]);
        }
        __syncthreads();
    }
    #pragma unroll
    for (int j = 0; j < 4; j++)
        rt[((size_t)b * kN + t0 + tg * 4 + j) * kR + r] = acc[j];
}

// ---------------------------------------------------------------------------
// Consensus MLP update:
//   S_hat[b,s,t] += bm2 + sum_r relu(a_s[b,s,r] - b_t[b,t,r]) * Wm2[r]
// grid (t_tiles=4 [128], s_tiles=8 [64], b=8), block 256 = 16x16, 4s x 8t micro
// ---------------------------------------------------------------------------
__global__ void mlp_kernel(const float* __restrict__ a_s, const float* __restrict__ b_t,
                           const float* __restrict__ Wm2, const float* __restrict__ bm2,
                           float* __restrict__ shat)
{
    __shared__ float Asm[64][33];
    __shared__ float Bsm[128][33];
    __shared__ float w2[32];
    int b = blockIdx.z;
    int s0 = blockIdx.y * 64;
    int t0 = blockIdx.x * 128;
    int tid = threadIdx.x;
    if (tid < 32) w2[tid] = Wm2[tid];
    const float* Ab = a_s + ((size_t)b * kN + s0) * kR;
    for (int i = tid; i < 64 * 32; i += 256) Asm[i >> 5][i & 31] = Ab[i];
    const float* Bb = b_t + ((size_t)b * kN + t0) * kR;
    for (int i = tid; i < 128 * 32; i += 256) Bsm[i >> 5][i & 31] = Bb[i];
    __syncthreads();
    int tx = tid & 15, ty = tid >> 4;
    float acc[4][8];
    #pragma unroll
    for (int i = 0; i < 4; i++)
        #pragma unroll
        for (int j = 0; j < 8; j++) acc[i][j] = 0.f;
    #pragma unroll 4
    for (int r = 0; r < 32; r++) {
        float w = w2[r];
        float av[4], bv[8];
        #pragma unroll
        for (int i = 0; i < 4; i++) av[i] = Asm[ty + i * 16][r];
        #pragma unroll
        for (int j = 0; j < 8; j++) bv[j] = Bsm[tx + j * 16][r];
        #pragma unroll
        for (int i = 0; i < 4; i++)
            #pragma unroll
            for (int j = 0; j < 8; j++) {
                float d = fmaxf(av[i] - bv[j], 0.f);
                acc[i][j] = fmaf(d, w, acc[i][j]);
            }
    }
    float bm2v = bm2[0];
    float* Sb = shat + ((size_t)b * kN + s0) * kN + t0;
    #pragma unroll
    for (int i = 0; i < 4; i++) {
        int s = ty + i * 16;
        #pragma unroll
        for (int j = 0; j < 8; j++) {
            int t = tx + j * 16;
            Sb[(size_t)s * kN + t] += acc[i][j] + bm2v;
        }
    }
}

// ---------------------------------------------------------------------------
// Host launch
// ---------------------------------------------------------------------------
extern "C" void kernel_launch(void* const* d_in, const int* in_sizes, int n_in,
                              void* d_out, int out_size)
{
    (void)in_sizes; (void)n_in; (void)out_size;
    const float* x_s     = (const float*)d_in[0];
    const int*   ei_s    = (const int*)  d_in[1];
    const float* ea_s    = (const float*)d_in[2];
    const float* x_t     = (const float*)d_in[4];
    const int*   ei_t    = (const int*)  d_in[5];
    const float* ea_t    = (const float*)d_in[6];
    const float* r_all   = (const float*)d_in[8];
    const float* W1_root = (const float*)d_in[9];
    const float* W1_nbr  = (const float*)d_in[10];
    const float* b1      = (const float*)d_in[11];
    const float* W2_root = (const float*)d_in[12];
    const float* W2_nbr  = (const float*)d_in[13];
    const float* b2      = (const float*)d_in[14];
    const float* Wm1     = (const float*)d_in[15];
    const float* bm1     = (const float*)d_in[16];
    const float* Wm2     = (const float*)d_in[17];
    const float* bm2     = (const float*)d_in[18];

    float* outS0 = (float*)d_out;
    float* outSL = outS0 + SZ_S;

    float* sc = nullptr;
    cudaGetSymbolAddress((void**)&sc, g_scratch);
    float* ys     = sc + OFF_YS;
    float* yt     = sc + OFF_YT;
    float* agg64s = sc + OFF_AGG64S;
    float* agg64t = sc + OFF_AGG64T;
    float* hs     = sc + OFF_HS;
    float* ht     = sc + OFF_HT;
    float* Shat   = sc + OFF_SHAT;
    float* Snorm  = sc + OFF_SNORM;
    float* tmpA   = sc + OFF_TMPA;
    float* tmpB   = sc + OFF_TMPB;
    float* agg32  = sc + OFF_AGG32;
    float* rtbuf  = sc + OFF_RT;
    float* asbuf  = sc + OFF_AS;
    float* btbuf  = sc + OFF_BT;

    const int* src_s = ei_s;
    const int* dst_s = ei_s + kE;
    const int* src_t = ei_t;
    const int* dst_t = ei_t + kE;

    // ---- psi_1 ------------------------------------------------------------
    zero_kernel<<<(int)(2 * SZ_NTDH + 255) / 256, 256>>>(agg64s, (int)(2 * SZ_NTDH));
    rowgemm<128, 64, 4, false, false, false><<<kNT / 4, 64>>>(x_s, W1_nbr, nullptr, nullptr, ys);
    rowgemm<128, 64, 4, false, false, false><<<kNT / 4, 64>>>(x_t, W1_nbr, nullptr, nullptr, yt);
    scatter_kernel<64><<<(kE * 16) / 256, 256>>>(ys, src_s, dst_s, ea_s, agg64s);
    scatter_kernel<64><<<(kE * 16) / 256, 256>>>(yt, src_t, dst_t, ea_t, agg64t);
    rowgemm<128, 64, 4, true, true, true><<<kNT / 4, 64>>>(x_s, W1_root, b1, agg64s, hs);
    rowgemm<128, 64, 4, true, true, true><<<kNT / 4, 64>>>(x_t, W1_root, b1, agg64t, ht);

    // ---- S_hat0 -----------------------------------------------------------
    gemm_nt_kernel<<<dim3(8, 8, 8), 256>>>(hs, ht, Shat);

    // ---- precompute a_s = psi2_s(r_s[k]) @ Wm1 + bm1 for both steps --------
    for (int k = 0; k < 2; k++) {
        const float* rsk = r_all + (size_t)k * SZ_NTR;
        float* ask = asbuf + (size_t)k * SZ_NTR;
        rowgemm<32, 32, 4, false, false, false><<<kNT / 4, 32>>>(rsk, W2_nbr, nullptr, nullptr, tmpA);
        zero_kernel<<<(int)(SZ_NTR + 255) / 256, 256>>>(agg32, (int)SZ_NTR);
        scatter_kernel<32><<<(kE * 8) / 256, 256>>>(tmpA, src_s, dst_s, ea_s, agg32);
        rowgemm<32, 32, 4, true, true, true><<<kNT / 4, 32>>>(rsk, W2_root, b2, agg32, tmpB);
        rowgemm<32, 32, 4, false, true, false><<<kNT / 4, 32>>>(tmpB, Wm1, bm1, nullptr, ask);
    }

    // ---- consensus steps ----------------------------------------------------
    for (int k = 0; k < 2; k++) {
        const float* rsk = r_all + (size_t)k * SZ_NTR;
        float* dest = (k == 0) ? outS0 : Snorm;  // step-0 softmax IS the S_0 output
        softmax_kernel<<<kNT, 128>>>(Shat, dest);
        rt_gemm_kernel<<<dim3(16, 8), 256>>>(dest, rsk, rtbuf);
        // psi2 on t-graph with r_t
        rowgemm<32, 32, 4, false, false, false><<<kNT / 4, 32>>>(rtbuf, W2_nbr, nullptr, nullptr, tmpA);
        zero_kernel<<<(int)(SZ_NTR + 255) / 256, 256>>>(agg32, (int)SZ_NTR);
        scatter_kernel<32><<<(kE * 8) / 256, 256>>>(tmpA, src_t, dst_t, ea_t, agg32);
        rowgemm<32, 32, 4, true, true, true><<<kNT / 4, 32>>>(rtbuf, W2_root, b2, agg32, tmpB);
        rowgemm<32, 32, 4, false, false, false><<<kNT / 4, 32>>>(tmpB, Wm1, nullptr, nullptr, btbuf);
        // S_hat += mlp(a_s - b_t)
        mlp_kernel<<<dim3(4, 8, 8), 256>>>(asbuf + (size_t)k * SZ_NTR, btbuf, Wm2, bm2, Shat);
    }

    // ---- final softmax -> S_L ----------------------------------------------
    softmax_kernel<<<kNT, 128>>>(Shat, outSL);
}

// round 2
// speedup vs baseline: 1.1804x; 1.1804x over previous
#include <cuda_runtime.h>
#include <cstdint>

// ---------------------------------------------------------------------------
// Problem constants
// ---------------------------------------------------------------------------
constexpr int kB   = 8;
constexpr int kN   = 512;
constexpr int kE   = 65536;
constexpr int kNT  = kB * kN;      // 4096
constexpr int kDIN = 128;
constexpr int kDH  = 64;
constexpr int kR   = 32;

constexpr size_t SZ_NTDH = (size_t)kNT * kDH;     // 262144
constexpr size_t SZ_NTR  = (size_t)kNT * kR;      // 131072
constexpr size_t SZ_S    = (size_t)kB * kN * kN;  // 2097152

// ---------------------------------------------------------------------------
// Scratch layout (atomic agg buffers first, contiguous, zeroed once)
// ---------------------------------------------------------------------------
constexpr size_t OFF_AGG64S = 0;
constexpr size_t OFF_AGG64T = OFF_AGG64S + SZ_NTDH;
constexpr size_t OFF_AGG32  = OFF_AGG64T + SZ_NTDH;   // 4 slots: s-step0, s-step1, t-step0, t-step1
constexpr size_t OFF_YS     = OFF_AGG32  + 4 * SZ_NTR;
constexpr size_t OFF_YT     = OFF_YS     + SZ_NTDH;
constexpr size_t OFF_HS     = OFF_YT     + SZ_NTDH;
constexpr size_t OFF_HT     = OFF_HS     + SZ_NTDH;
constexpr size_t OFF_SHAT   = OFF_HT     + SZ_NTDH;
constexpr size_t OFF_SNORM  = OFF_SHAT   + SZ_S;
constexpr size_t OFF_RT     = OFF_SNORM  + SZ_S;
constexpr size_t OFF_AS     = OFF_RT     + SZ_NTR;    // 2 steps contiguous
constexpr size_t OFF_BT     = OFF_AS     + 2 * SZ_NTR;
constexpr size_t SCRATCH_TOTAL = OFF_BT + SZ_NTR;

__device__ float g_scratch[SCRATCH_TOTAL];

constexpr size_t ZERO_SPAN = 2 * SZ_NTDH + 4 * SZ_NTR;  // = 1048576 floats
static_assert(ZERO_SPAN == 1048576, "zero span");

// ---------------------------------------------------------------------------
// Zero all atomic-aggregate buffers in one shot (float4)
// ---------------------------------------------------------------------------
__global__ void zero4_kernel(float4* __restrict__ p) {
    size_t i = (size_t)blockIdx.x * 256 + threadIdx.x;
    p[i] = make_float4(0.f, 0.f, 0.f, 0.f);
}

// ---------------------------------------------------------------------------
// Dual-instance row GEMM: instance picked by blockIdx.y (s-graph / t-graph).
// out[row, j] = act( bias[j] + sum_k A[row,k]*W[k,j] (+ add[row,j]) )
// ---------------------------------------------------------------------------
template<int K, int Nc, int RPB, bool RELU, bool HASBIAS, bool HASADD>
__global__ void rowgemm2(const float* __restrict__ A0, const float* __restrict__ A1,
                         const float* __restrict__ W,  const float* __restrict__ bias,
                         const float* __restrict__ add0, const float* __restrict__ add1,
                         float* __restrict__ out0, float* __restrict__ out1)
{
    const float* A   = blockIdx.y == 0 ? A0   : A1;
    const float* add = blockIdx.y == 0 ? add0 : add1;
    float*       out = blockIdx.y == 0 ? out0 : out1;

    __shared__ float As[RPB][K];
    int row0 = blockIdx.x * RPB;
    int j = threadIdx.x;
    for (int i = j; i < RPB * K; i += Nc) As[i / K][i % K] = A[(size_t)row0 * K + i];
    __syncthreads();
    float acc[RPB];
    #pragma unroll
    for (int rr = 0; rr < RPB; rr++) acc[rr] = HASBIAS ? bias[j] : 0.f;
    #pragma unroll 4
    for (int k = 0; k < K; k++) {
        float w = W[k * Nc + j];
        #pragma unroll
        for (int rr = 0; rr < RPB; rr++) acc[rr] = fmaf(As[rr][k], w, acc[rr]);
    }
    #pragma unroll
    for (int rr = 0; rr < RPB; rr++) {
        float v = acc[rr];
        if (HASADD) v += add[(size_t)(row0 + rr) * Nc + j];
        if (RELU)   v = fmaxf(v, 0.f);
        out[(size_t)(row0 + rr) * Nc + j] = v;
    }
}

// ---------------------------------------------------------------------------
// psi_1 scatter, both graphs in one launch (blockIdx.y): agg[dst] += y[src]*ea
// ---------------------------------------------------------------------------
__global__ void scat64_both(const float* __restrict__ ys, const float* __restrict__ yt,
                            const int* __restrict__ eis, const int* __restrict__ eit,
                            const float* __restrict__ eas, const float* __restrict__ eat,
                            float* __restrict__ aggs, float* __restrict__ aggt)
{
    const float* y   = blockIdx.y == 0 ? ys  : yt;
    const int*   ei  = blockIdx.y == 0 ? eis : eit;
    const float* ea  = blockIdx.y == 0 ? eas : eat;
    float*       agg = blockIdx.y == 0 ? aggs : aggt;
    const int* src = ei;
    const int* dst = ei + kE;

    constexpr int C = 16;  // 64 floats / 4
    int tid = blockIdx.x * blockDim.x + threadIdx.x;
    int e = tid / C, c = tid % C;
    if (e >= kE) return;
    int s = src[e], d = dst[e];
    float w = ea[e];
    float4 v = *reinterpret_cast<const float4*>(y + (size_t)s * 64 + c * 4);
    float* p = agg + (size_t)d * 64 + c * 4;
    asm volatile("red.global.add.v4.f32 [%0], {%1,%2,%3,%4};"
                 :: "l"(p), "f"(v.x * w), "f"(v.y * w), "f"(v.z * w), "f"(v.w * w)
                 : "memory");
}

// ---------------------------------------------------------------------------
// psi_2 scatter on RAW r (linearity: W2_nbr applied after aggregation).
// blockIdx.y = instance; y/agg advance by stride per instance.
// ---------------------------------------------------------------------------
__global__ void scat32_strided(const float* __restrict__ ybase, const int* __restrict__ ei,
                               const float* __restrict__ ea, float* __restrict__ aggbase,
                               size_t stride)
{
    const float* y   = ybase   + (size_t)blockIdx.y * stride;
    float*       agg = aggbase + (size_t)blockIdx.y * stride;
    const int* src = ei;
    const int* dst = ei + kE;

    constexpr int C = 8;   // 32 floats / 4
    int tid = blockIdx.x * blockDim.x + threadIdx.x;
    int e = tid / C, c = tid % C;
    if (e >= kE) return;
    int s = src[e], d = dst[e];
    float w = ea[e];
    float4 v = *reinterpret_cast<const float4*>(y + (size_t)s * 32 + c * 4);
    float* p = agg + (size_t)d * 32 + c * 4;
    asm volatile("red.global.add.v4.f32 [%0], {%1,%2,%3,%4};"
                 :: "l"(p), "f"(v.x * w), "f"(v.y * w), "f"(v.z * w), "f"(v.w * w)
                 : "memory");
}

// ---------------------------------------------------------------------------
// Fused psi_2 + Wm1 projection:
//   o   = relu( r @ W2_root + agg @ W2_nbr + b2 )        [row, 32]
//   out = o @ Wm1 (+ bm1 if hasBm1)                      [row, 32]
// block 256 = 8 warps, each warp owns 4 rows. grid.y = instance (stride SZ_NTR).
// ---------------------------------------------------------------------------
__global__ void psi2_kernel(const float* __restrict__ rbase, const float* __restrict__ aggbase,
                            const float* __restrict__ W2_root, const float* __restrict__ W2_nbr,
                            const float* __restrict__ b2, const float* __restrict__ Wm1,
                            const float* __restrict__ bm1, float* __restrict__ outbase,
                            int hasBm1)
{
    const float* r   = rbase   + (size_t)blockIdx.y * SZ_NTR;
    const float* agg = aggbase + (size_t)blockIdx.y * SZ_NTR;
    float*       out = outbase + (size_t)blockIdx.y * SZ_NTR;

    __shared__ float rsm[8][4][33];
    __shared__ float gsm[8][4][33];
    __shared__ float osm[8][4][33];

    int warp = threadIdx.x >> 5, lane = threadIdx.x & 31;
    int row0 = blockIdx.x * 32 + warp * 4;

    #pragma unroll
    for (int rr = 0; rr < 4; rr++) {
        rsm[warp][rr][lane] = r[(size_t)(row0 + rr) * 32 + lane];
        gsm[warp][rr][lane] = agg[(size_t)(row0 + rr) * 32 + lane];
    }
    __syncwarp();

    float o[4];
    float bv = b2[lane];
    #pragma unroll
    for (int rr = 0; rr < 4; rr++) o[rr] = bv;
    #pragma unroll 4
    for (int k = 0; k < 32; k++) {
        float wr = W2_root[k * 32 + lane];
        float wn = W2_nbr [k * 32 + lane];
        #pragma unroll
        for (int rr = 0; rr < 4; rr++) {
            o[rr] = fmaf(rsm[warp][rr][k], wr, o[rr]);
            o[rr] = fmaf(gsm[warp][rr][k], wn, o[rr]);
        }
    }
    #pragma unroll
    for (int rr = 0; rr < 4; rr++) osm[warp][rr][lane] = fmaxf(o[rr], 0.f);
    __syncwarp();

    float a[4];
    float b0 = hasBm1 ? bm1[lane] : 0.f;
    #pragma unroll
    for (int rr = 0; rr < 4; rr++) a[rr] = b0;
    #pragma unroll 4
    for (int k = 0; k < 32; k++) {
        float w = Wm1[k * 32 + lane];
        #pragma unroll
        for (int rr = 0; rr < 4; rr++) a[rr] = fmaf(osm[warp][rr][k], w, a[rr]);
    }
    #pragma unroll
    for (int rr = 0; rr < 4; rr++) out[(size_t)(row0 + rr) * 32 + lane] = a[rr];
}

// ---------------------------------------------------------------------------
// Fused S_hat0 GEMM-NT + row softmax.
// Block owns (b, 8 full s-rows). Writes raw Shat0 AND normalized S_0.
// ---------------------------------------------------------------------------
__global__ void gemm_softmax_kernel(const float* __restrict__ hs, const float* __restrict__ ht,
                                    float* __restrict__ shat, float* __restrict__ snorm)
{
    __shared__ float hsS[8][64];
    __shared__ float htS[64][65];
    __shared__ float Ssm[8][512];

    int b  = blockIdx.x >> 6;
    int s0 = (blockIdx.x & 63) * 8;
    int tid = threadIdx.x;

    const float* hsb = hs + ((size_t)b * kN + s0) * kDH;
    for (int i = tid; i < 8 * 64; i += 256) hsS[i >> 6][i & 63] = hsb[i];

    int tloc = tid & 63;
    int sgrp = tid >> 6;           // 0..3 -> rows sgrp*2, sgrp*2+1

    for (int tt = 0; tt < 8; tt++) {
        __syncthreads();
        const float* htb = ht + ((size_t)b * kN + tt * 64) * kDH;
        for (int i = tid; i < 64 * 64; i += 256) htS[i >> 6][i & 63] = htb[i];
        __syncthreads();

        float acc0 = 0.f, acc1 = 0.f;
        #pragma unroll 8
        for (int k = 0; k < 64; k++) {
            float hv = htS[tloc][k];
            acc0 = fmaf(hsS[sgrp * 2][k],     hv, acc0);
            acc1 = fmaf(hsS[sgrp * 2 + 1][k], hv, acc1);
        }
        int t = tt * 64 + tloc;
        Ssm[sgrp * 2][t]     = acc0;
        Ssm[sgrp * 2 + 1][t] = acc1;
        shat[((size_t)(b * kN + s0 + sgrp * 2))     * kN + t] = acc0;
        shat[((size_t)(b * kN + s0 + sgrp * 2 + 1)) * kN + t] = acc1;
    }
    __syncthreads();

    // softmax: warp w -> row w
    int w = tid >> 5, lane = tid & 31;
    float v[16], m = -3.4e38f;
    #pragma unroll
    for (int i = 0; i < 16; i++) { v[i] = Ssm[w][lane + 32 * i]; m = fmaxf(m, v[i]); }
    #pragma unroll
    for (int o = 16; o > 0; o >>= 1) m = fmaxf(m, __shfl_xor_sync(0xffffffffu, m, o));
    float s = 0.f;
    #pragma unroll
    for (int i = 0; i < 16; i++) { v[i] = __expf(v[i] - m); s += v[i]; }
    #pragma unroll
    for (int o = 16; o > 0; o >>= 1) s += __shfl_xor_sync(0xffffffffu, s, o);
    float inv = 1.f / s;
    float* dst = snorm + ((size_t)(b * kN + s0 + w)) * kN;
    #pragma unroll
    for (int i = 0; i < 16; i++) dst[lane + 32 * i] = v[i] * inv;
}

// ---------------------------------------------------------------------------
// r_t[b,t,r] = sum_s S[b,s,t] * r_s[b,s,r]    (S normalized)
// ---------------------------------------------------------------------------
__global__ void rt_gemm_kernel(const float* __restrict__ S, const float* __restrict__ rs,
                               float* __restrict__ rt)
{
    __shared__ float Ssm[8][32];
    __shared__ float Rsm[8][32];
    int b = blockIdx.y, t0 = blockIdx.x * 32;
    int tid = threadIdx.x;
    int r = tid & 31, tg = tid >> 5;
    const float* Sb = S + (size_t)b * kN * kN;
    const float* Rb = rs + (size_t)b * kN * kR;
    float acc[4] = {0.f, 0.f, 0.f, 0.f};
    for (int s0 = 0; s0 < kN; s0 += 8) {
        Ssm[tg][r] = Sb[(size_t)(s0 + tg) * kN + t0 + r];
        Rsm[tg][r] = Rb[(size_t)(s0 + tg) * kR + r];
        __syncthreads();
        #pragma unroll
        for (int q = 0; q < 8; q++) {
            float rv = Rsm[q][r];
            #pragma unroll
            for (int j = 0; j < 4; j++)
                acc[j] = fmaf(Ssm[q][tg * 4 + j], rv, acc[j]);
        }
        __syncthreads();
    }
    #pragma unroll
    for (int j = 0; j < 4; j++)
        rt[((size_t)b * kN + t0 + tg * 4 + j) * kR + r] = acc[j];
}

// ---------------------------------------------------------------------------
// Fused consensus-MLP + S_hat RMW + row softmax.
//   v[s,t] = shat_in[s,t] + bm2 + sum_r relu(a_s[s,r] - b_t[t,r]) * Wm2[r]
//   (writeShat) shat_out = v ;  snorm_out = softmax_rows(v)
// Block owns (b, 8 full s-rows); t tiled by 128.
// ---------------------------------------------------------------------------
__global__ void mlp_softmax_kernel(const float* __restrict__ shat_in,
                                   const float* __restrict__ a_s, const float* __restrict__ b_t,
                                   const float* __restrict__ Wm2, const float* __restrict__ bm2,
                                   float* __restrict__ shat_out, float* __restrict__ snorm_out,
                                   int writeShat)
{
    __shared__ float Asm[8][33];
    __shared__ float Bsm[128][33];
    __shared__ float Ssm[8][512];
    __shared__ float w2[32];

    int b  = blockIdx.x >> 6;
    int s0 = (blockIdx.x & 63) * 8;
    int tid = threadIdx.x;

    if (tid < 32) w2[tid] = Wm2[tid];
    const float* Ab = a_s + ((size_t)b * kN + s0) * kR;
    for (int i = tid; i < 8 * 32; i += 256) Asm[i >> 5][i & 31] = Ab[i];
    float bm2v = bm2[0];

    int tl = tid & 127;
    int sg = tid >> 7;             // 0..1 -> rows sg*4 .. sg*4+3

    for (int tt = 0; tt < 4; tt++) {
        int t0 = tt * 128;
        __syncthreads();
        const float* Bb = b_t + ((size_t)b * kN + t0) * kR;
        for (int i = tid; i < 128 * 32; i += 256) Bsm[i >> 5][i & 31] = Bb[i];
        __syncthreads();

        float acc[4] = {0.f, 0.f, 0.f, 0.f};
        #pragma unroll 4
        for (int r = 0; r < 32; r++) {
            float w  = w2[r];
            float bv = Bsm[tl][r];
            #pragma unroll
            for (int si = 0; si < 4; si++) {
                float d = fmaxf(Asm[sg * 4 + si][r] - bv, 0.f);
                acc[si] = fmaf(d, w, acc[si]);
            }
        }
        #pragma unroll
        for (int si = 0; si < 4; si++) {
            int s = sg * 4 + si;
            size_t idx = ((size_t)(b * kN + s0 + s)) * kN + t0 + tl;
            float v = shat_in[idx] + acc[si] + bm2v;
            Ssm[s][t0 + tl] = v;
            if (writeShat) shat_out[idx] = v;
        }
    }
    __syncthreads();

    int w = tid >> 5, lane = tid & 31;
    float v[16], m = -3.4e38f;
    #pragma unroll
    for (int i = 0; i < 16; i++) { v[i] = Ssm[w][lane + 32 * i]; m = fmaxf(m, v[i]); }
    #pragma unroll
    for (int o = 16; o > 0; o >>= 1) m = fmaxf(m, __shfl_xor_sync(0xffffffffu, m, o));
    float s = 0.f;
    #pragma unroll
    for (int i = 0; i < 16; i++) { v[i] = __expf(v[i] - m); s += v[i]; }
    #pragma unroll
    for (int o = 16; o > 0; o >>= 1) s += __shfl_xor_sync(0xffffffffu, s, o);
    float inv = 1.f / s;
    float* dst = snorm_out + ((size_t)(b * kN + s0 + w)) * kN;
    #pragma unroll
    for (int i = 0; i < 16; i++) dst[lane + 32 * i] = v[i] * inv;
}

// ---------------------------------------------------------------------------
// Host launch (14 kernels, single stream)
// ---------------------------------------------------------------------------
extern "C" void kernel_launch(void* const* d_in, const int* in_sizes, int n_in,
                              void* d_out, int out_size)
{
    (void)in_sizes; (void)n_in; (void)out_size;
    const float* x_s     = (const float*)d_in[0];
    const int*   ei_s    = (const int*)  d_in[1];
    const float* ea_s    = (const float*)d_in[2];
    const float* x_t     = (const float*)d_in[4];
    const int*   ei_t    = (const int*)  d_in[5];
    const float* ea_t    = (const float*)d_in[6];
    const float* r_all   = (const float*)d_in[8];
    const float* W1_root = (const float*)d_in[9];
    const float* W1_nbr  = (const float*)d_in[10];
    const float* b1      = (const float*)d_in[11];
    const float* W2_root = (const float*)d_in[12];
    const float* W2_nbr  = (const float*)d_in[13];
    const float* b2      = (const float*)d_in[14];
    const float* Wm1     = (const float*)d_in[15];
    const float* bm1     = (const float*)d_in[16];
    const float* Wm2     = (const float*)d_in[17];
    const float* bm2     = (const float*)d_in[18];

    float* outS0 = (float*)d_out;
    float* outSL = outS0 + SZ_S;

    float* sc = nullptr;
    cudaGetSymbolAddress((void**)&sc, g_scratch);
    float* agg64s = sc + OFF_AGG64S;
    float* agg64t = sc + OFF_AGG64T;
    float* agg32  = sc + OFF_AGG32;   // 4 slots
    float* ys     = sc + OFF_YS;
    float* yt     = sc + OFF_YT;
    float* hs     = sc + OFF_HS;
    float* ht     = sc + OFF_HT;
    float* Shat   = sc + OFF_SHAT;
    float* Snorm  = sc + OFF_SNORM;
    float* rtbuf  = sc + OFF_RT;
    float* asbuf  = sc + OFF_AS;
    float* btbuf  = sc + OFF_BT;

    // K1: zero all atomic buffers (one contiguous span)
    zero4_kernel<<<1024, 256>>>((float4*)(sc + OFF_AGG64S));

    // K2: y = x @ W1_nbr for s & t
    rowgemm2<128, 64, 8, false, false, false><<<dim3(kNT / 8, 2), 64>>>(
        x_s, x_t, W1_nbr, nullptr, nullptr, nullptr, ys, yt);

    // K3: raw-r scatter on s-graph for both steps (linearity trick)
    scat32_strided<<<dim3((kE * 8) / 256, 2), 256>>>(r_all, ei_s, ea_s, agg32, SZ_NTR);

    // K4: psi_1 scatter, both graphs
    scat64_both<<<dim3((kE * 16) / 256, 2), 256>>>(ys, yt, ei_s, ei_t, ea_s, ea_t, agg64s, agg64t);

    // K5: h = relu(x @ W1_root + b1 + agg64), both graphs
    rowgemm2<128, 64, 8, true, true, true><<<dim3(kNT / 8, 2), 64>>>(
        x_s, x_t, W1_root, b1, agg64s, agg64t, hs, ht);

    // K6: a_s[k] = relu(r_k@W2_root + agg32_s[k]@W2_nbr + b2) @ Wm1 + bm1, both steps
    psi2_kernel<<<dim3(kNT / 32, 2), 256>>>(r_all, agg32, W2_root, W2_nbr, b2, Wm1, bm1, asbuf, 1);

    // K7: S_hat0 + softmax -> Shat, outS0
    gemm_softmax_kernel<<<512, 256>>>(hs, ht, Shat, outS0);

    // ---- step 0 ----
    rt_gemm_kernel<<<dim3(16, 8), 256>>>(outS0, r_all, rtbuf);
    scat32_strided<<<dim3((kE * 8) / 256, 1), 256>>>(rtbuf, ei_t, ea_t, agg32 + 2 * SZ_NTR, 0);
    psi2_kernel<<<dim3(kNT / 32, 1), 256>>>(rtbuf, agg32 + 2 * SZ_NTR, W2_root, W2_nbr, b2,
                                            Wm1, nullptr, btbuf, 0);
    mlp_softmax_kernel<<<512, 256>>>(Shat, asbuf, btbuf, Wm2, bm2, Shat, Snorm, 1);

    // ---- step 1 ----
    rt_gemm_kernel<<<dim3(16, 8), 256>>>(Snorm, r_all + SZ_NTR, rtbuf);
    scat32_strided<<<dim3((kE * 8) / 256, 1), 256>>>(rtbuf, ei_t, ea_t, agg32 + 3 * SZ_NTR, 0);
    psi2_kernel<<<dim3(kNT / 32, 1), 256>>>(rtbuf, agg32 + 3 * SZ_NTR, W2_root, W2_nbr, b2,
                                            Wm1, nullptr, btbuf, 0);
    mlp_softmax_kernel<<<512, 256>>>(Shat, asbuf + SZ_NTR, btbuf, Wm2, bm2, nullptr, outSL, 0);
}

// round 3
// speedup vs baseline: 1.3877x; 1.1756x over previous
#include <cuda_runtime.h>
#include <cstdint>

// ---------------------------------------------------------------------------
// Problem constants
// ---------------------------------------------------------------------------
constexpr int kB   = 8;
constexpr int kN   = 512;
constexpr int kE   = 65536;
constexpr int kNT  = kB * kN;      // 4096
constexpr int kDH  = 64;
constexpr int kR   = 32;

constexpr size_t SZ_NTDH = (size_t)kNT * kDH;     // 262144
constexpr size_t SZ_NTR  = (size_t)kNT * kR;      // 131072
constexpr size_t SZ_S    = (size_t)kB * kN * kN;  // 2097152

// ---------------------------------------------------------------------------
// Scratch layout. Buffers zeroed by the proj kernel come first:
//   agg64s, agg64t, agg32 s-graph step0, agg32 s-graph step1  (=786432 floats)
// agg32_t (t-graph slot) is zeroed inside step_mid itself.
// ---------------------------------------------------------------------------
constexpr size_t OFF_AGG64S = 0;
constexpr size_t OFF_AGG64T = OFF_AGG64S + SZ_NTDH;
constexpr size_t OFF_AGG32S = OFF_AGG64T + SZ_NTDH;   // 2 slots (steps 0,1)
constexpr size_t OFF_AGG32T = OFF_AGG32S + 2 * SZ_NTR;
constexpr size_t OFF_YS     = OFF_AGG32T + SZ_NTR;
constexpr size_t OFF_YT     = OFF_YS     + SZ_NTDH;
constexpr size_t OFF_HS     = OFF_YT     + SZ_NTDH;
constexpr size_t OFF_HT     = OFF_HS     + SZ_NTDH;
constexpr size_t OFF_SHAT   = OFF_HT     + SZ_NTDH;
constexpr size_t OFF_SNORM  = OFF_SHAT   + SZ_S;
constexpr size_t OFF_RT     = OFF_SNORM  + SZ_S;
constexpr size_t OFF_AS     = OFF_RT     + SZ_NTR;    // 2 steps
constexpr size_t OFF_BT     = OFF_AS     + 2 * SZ_NTR;
constexpr size_t SCRATCH_TOTAL = OFF_BT + SZ_NTR;

__device__ float g_scratch[SCRATCH_TOTAL];

// Ticket grid barrier (monotonic counter: safe across launches & graph replays)
__device__ unsigned int g_bar = 0;

__device__ __forceinline__ void grid_bar(int nblk) {
    __syncthreads();
    __threadfence();
    if (threadIdx.x == 0) {
        unsigned old = atomicAdd(&g_bar, 1u);
        unsigned target = (old / nblk + 1u) * nblk;
        while (*(volatile unsigned*)&g_bar < target) { }
    }
    __syncthreads();
    __threadfence();
}

// ---------------------------------------------------------------------------
// K1: projection (x @ W1_nbr, both graphs) + zero atomic buffers.
// grid (256, 5), block 256.
//   y=0,1 : proj s/t — 16 rows/block, thread = (col 64) x (rowgroup 4), 4 rows each
//   y=2..4: zero 262144 floats each (786432 total)
// ---------------------------------------------------------------------------
__global__ __launch_bounds__(256) void proj_zero_kernel(
    const float* __restrict__ x_s, const float* __restrict__ x_t,
    const float* __restrict__ W, float* __restrict__ ys, float* __restrict__ yt,
    float* __restrict__ zerobase)
{
    int y = blockIdx.y;
    int tid = threadIdx.x;
    if (y >= 2) {
        size_t i = (size_t)(y - 2) * 65536 + (size_t)blockIdx.x * 256 + tid;
        reinterpret_cast<float4*>(zerobase)[i] = make_float4(0.f, 0.f, 0.f, 0.f);
        return;
    }
    const float* A = y == 0 ? x_s : x_t;
    float*       out = y == 0 ? ys : yt;

    __shared__ float As[16][128];
    int row0 = blockIdx.x * 16;
    for (int i = tid; i < 16 * 128; i += 256)
        As[i >> 7][i & 127] = A[(size_t)row0 * 128 + i];
    __syncthreads();

    int j = tid & 63, g = tid >> 6;
    float acc[4] = {0.f, 0.f, 0.f, 0.f};
    #pragma unroll 4
    for (int k = 0; k < 128; k++) {
        float w = __ldg(&W[k * 64 + j]);
        #pragma unroll
        for (int rr = 0; rr < 4; rr++)
            acc[rr] = fmaf(As[g * 4 + rr][k], w, acc[rr]);
    }
    #pragma unroll
    for (int rr = 0; rr < 4; rr++)
        out[(size_t)(row0 + g * 4 + rr) * 64 + j] = acc[rr];
}

// ---------------------------------------------------------------------------
// K3: root GEMM: h = relu(x @ W1_root + b1 + agg), both graphs. grid (256,2)
// ---------------------------------------------------------------------------
__global__ __launch_bounds__(256) void root_kernel(
    const float* __restrict__ x_s, const float* __restrict__ x_t,
    const float* __restrict__ W, const float* __restrict__ bias,
    const float* __restrict__ agg_s, const float* __restrict__ agg_t,
    float* __restrict__ hs, float* __restrict__ ht)
{
    int y = blockIdx.y;
    const float* A   = y == 0 ? x_s   : x_t;
    const float* add = y == 0 ? agg_s : agg_t;
    float*       out = y == 0 ? hs    : ht;

    __shared__ float As[16][128];
    int tid = threadIdx.x;
    int row0 = blockIdx.x * 16;
    for (int i = tid; i < 16 * 128; i += 256)
        As[i >> 7][i & 127] = A[(size_t)row0 * 128 + i];
    __syncthreads();

    int j = tid & 63, g = tid >> 6;
    float bv = bias[j];
    float acc[4] = {bv, bv, bv, bv};
    #pragma unroll 4
    for (int k = 0; k < 128; k++) {
        float w = __ldg(&W[k * 64 + j]);
        #pragma unroll
        for (int rr = 0; rr < 4; rr++)
            acc[rr] = fmaf(As[g * 4 + rr][k], w, acc[rr]);
    }
    #pragma unroll
    for (int rr = 0; rr < 4; rr++) {
        size_t idx = (size_t)(row0 + g * 4 + rr) * 64 + j;
        out[idx] = fmaxf(acc[rr] + add[idx], 0.f);
    }
}

// ---------------------------------------------------------------------------
// K2: all input-side scatters in one launch. grid (4096, 4), block 256.
//  y=0: psi_1 s-graph (64-wide, ys)   y=1: psi_1 t-graph (64-wide, yt)
//  y=2: raw-r s-graph step0 (32-wide) y=3: raw-r s-graph step1
// ---------------------------------------------------------------------------
__global__ __launch_bounds__(256) void scatter_all(
    const float* __restrict__ ys, const float* __restrict__ yt,
    const float* __restrict__ r_all,
    const int* __restrict__ eis, const int* __restrict__ eit,
    const float* __restrict__ eas, const float* __restrict__ eat,
    float* __restrict__ agg64s, float* __restrict__ agg64t,
    float* __restrict__ agg32s)
{
    int y = blockIdx.y;
    if (y < 2) {
        const float* src_y = y == 0 ? ys : yt;
        const int*   ei    = y == 0 ? eis : eit;
        const float* ea    = y == 0 ? eas : eat;
        float*       agg   = y == 0 ? agg64s : agg64t;
        int tid = blockIdx.x * 256 + threadIdx.x;
        int e = tid >> 4, c = tid & 15;
        int s = ei[e], d = ei[kE + e];
        float w = ea[e];
        float4 v = *reinterpret_cast<const float4*>(src_y + (size_t)s * 64 + c * 4);
        float* p = agg + (size_t)d * 64 + c * 4;
        asm volatile("red.global.add.v4.f32 [%0], {%1,%2,%3,%4};"
                     :: "l"(p), "f"(v.x * w), "f"(v.y * w), "f"(v.z * w), "f"(v.w * w)
                     : "memory");
    } else {
        if (blockIdx.x >= 2048) return;
        int step = y - 2;
        const float* src_y = r_all + (size_t)step * SZ_NTR;
        float*       agg   = agg32s + (size_t)step * SZ_NTR;
        int tid = blockIdx.x * 256 + threadIdx.x;
        int e = tid >> 3, c = tid & 7;
        int s = eis[e], d = eis[kE + e];
        float w = eas[e];
        float4 v = *reinterpret_cast<const float4*>(src_y + (size_t)s * 32 + c * 4);
        float* p = agg + (size_t)d * 32 + c * 4;
        asm volatile("red.global.add.v4.f32 [%0], {%1,%2,%3,%4};"
                     :: "l"(p), "f"(v.x * w), "f"(v.y * w), "f"(v.z * w), "f"(v.w * w)
                     : "memory");
    }
}

// ---------------------------------------------------------------------------
// psi_2 + Wm1 body (device function, used standalone and inside step_mid):
//   o   = relu( r @ W2_root + agg @ W2_nbr + b2 )
//   out = o @ Wm1 (+ bm1 if hasBm1)
// 128 blocks x 256 threads cover 4096 rows (32 rows/block, warp = 4 rows).
// ---------------------------------------------------------------------------
struct Psi2Smem {
    float rsm[8][4][33];
    float gsm[8][4][33];
    float osm[8][4][33];
};

__device__ __forceinline__ void psi2_body(
    Psi2Smem& sm, int bk,
    const float* __restrict__ r, const float* __restrict__ agg,
    const float* __restrict__ W2_root, const float* __restrict__ W2_nbr,
    const float* __restrict__ b2, const float* __restrict__ Wm1,
    const float* __restrict__ bm1, float* __restrict__ out, int hasBm1)
{
    int warp = threadIdx.x >> 5, lane = threadIdx.x & 31;
    int row0 = bk * 32 + warp * 4;

    #pragma unroll
    for (int rr = 0; rr < 4; rr++) {
        sm.rsm[warp][rr][lane] = r[(size_t)(row0 + rr) * 32 + lane];
        sm.gsm[warp][rr][lane] = agg[(size_t)(row0 + rr) * 32 + lane];
    }
    __syncwarp();

    float o[4];
    float bv = b2[lane];
    #pragma unroll
    for (int rr = 0; rr < 4; rr++) o[rr] = bv;
    #pragma unroll 4
    for (int k = 0; k < 32; k++) {
        float wr = W2_root[k * 32 + lane];
        float wn = W2_nbr [k * 32 + lane];
        #pragma unroll
        for (int rr = 0; rr < 4; rr++) {
            o[rr] = fmaf(sm.rsm[warp][rr][k], wr, o[rr]);
            o[rr] = fmaf(sm.gsm[warp][rr][k], wn, o[rr]);
        }
    }
    #pragma unroll
    for (int rr = 0; rr < 4; rr++) sm.osm[warp][rr][lane] = fmaxf(o[rr], 0.f);
    __syncwarp();

    float a[4];
    float b0 = hasBm1 ? bm1[lane] : 0.f;
    #pragma unroll
    for (int rr = 0; rr < 4; rr++) a[rr] = b0;
    #pragma unroll 4
    for (int k = 0; k < 32; k++) {
        float w = Wm1[k * 32 + lane];
        #pragma unroll
        for (int rr = 0; rr < 4; rr++) a[rr] = fmaf(sm.osm[warp][rr][k], w, a[rr]);
    }
    #pragma unroll
    for (int rr = 0; rr < 4; rr++) out[(size_t)(row0 + rr) * 32 + lane] = a[rr];
}

// K4: standalone psi2 for a_s precompute (both steps), grid (128, 2)
__global__ __launch_bounds__(256) void psi2_kernel(
    const float* __restrict__ rbase, const float* __restrict__ aggbase,
    const float* __restrict__ W2_root, const float* __restrict__ W2_nbr,
    const float* __restrict__ b2, const float* __restrict__ Wm1,
    const float* __restrict__ bm1, float* __restrict__ outbase)
{
    __shared__ Psi2Smem sm;
    const float* r   = rbase   + (size_t)blockIdx.y * SZ_NTR;
    const float* agg = aggbase + (size_t)blockIdx.y * SZ_NTR;
    float*       out = outbase + (size_t)blockIdx.y * SZ_NTR;
    psi2_body(sm, blockIdx.x, r, agg, W2_root, W2_nbr, b2, Wm1, bm1, out, 1);
}

// ---------------------------------------------------------------------------
// K5: fused S_hat0 GEMM-NT + register softmax.
// grid 256: b = blk>>5, s0 = (blk&31)*16. Block owns 16 full s-rows.
// Warp w owns rows s0+2w, s0+2w+1. Thread: 2s x 16t accumulators.
// ---------------------------------------------------------------------------
__global__ __launch_bounds__(256) void gemm_softmax_kernel(
    const float* __restrict__ hs, const float* __restrict__ ht,
    float* __restrict__ shat, float* __restrict__ snorm)
{
    __shared__ float hsS[16][64];
    __shared__ float htS[128][65];

    int b  = blockIdx.x >> 5;
    int s0 = (blockIdx.x & 31) * 16;
    int tid = threadIdx.x;
    int w = tid >> 5, lane = tid & 31;

    const float* hsb = hs + ((size_t)b * kN + s0) * kDH;
    for (int i = tid; i < 16 * 64; i += 256) hsS[i >> 6][i & 63] = hsb[i];

    float acc[2][16];
    #pragma unroll
    for (int i = 0; i < 2; i++)
        #pragma unroll
        for (int j = 0; j < 16; j++) acc[i][j] = 0.f;

    for (int tt = 0; tt < 4; tt++) {
        __syncthreads();
        const float* htb = ht + ((size_t)b * kN + tt * 128) * kDH;
        for (int i = tid; i < 128 * 64; i += 256) htS[i >> 6][i & 63] = htb[i];
        __syncthreads();

        #pragma unroll 4
        for (int k = 0; k < 64; k++) {
            float a0 = hsS[2 * w][k];
            float a1 = hsS[2 * w + 1][k];
            #pragma unroll
            for (int m = 0; m < 4; m++) {
                float hv = htS[lane + 32 * m][k];
                acc[0][tt * 4 + m] = fmaf(a0, hv, acc[0][tt * 4 + m]);
                acc[1][tt * 4 + m] = fmaf(a1, hv, acc[1][tt * 4 + m]);
            }
        }
    }

    // softmax per row from registers; j -> t = (j>>2)*128 + 32*(j&3) + lane
    #pragma unroll
    for (int si = 0; si < 2; si++) {
        int row = b * kN + s0 + 2 * w + si;
        float m = -3.4e38f;
        #pragma unroll
        for (int j = 0; j < 16; j++) m = fmaxf(m, acc[si][j]);
        #pragma unroll
        for (int o = 16; o > 0; o >>= 1) m = fmaxf(m, __shfl_xor_sync(0xffffffffu, m, o));
        float s = 0.f;
        float e[16];
        #pragma unroll
        for (int j = 0; j < 16; j++) { e[j] = __expf(acc[si][j] - m); s += e[j]; }
        #pragma unroll
        for (int o = 16; o > 0; o >>= 1) s += __shfl_xor_sync(0xffffffffu, s, o);
        float inv = 1.f / s;
        float* sh = shat + (size_t)row * kN;
        float* sn = snorm + (size_t)row * kN;
        #pragma unroll
        for (int j = 0; j < 16; j++) {
            int t = (j >> 2) * 128 + 32 * (j & 3) + lane;
            sh[t] = acc[si][j];
            sn[t] = e[j] * inv;
        }
    }
}

// ---------------------------------------------------------------------------
// K6/K8: fused per-step mid chain (persistent, grid 128, block 256):
//   phase A: zero agg32_t  +  rt = S^T @ r_s  (tiled GEMM, 2t x 2r micro)
//   grid_bar
//   phase B: t-graph raw-r scatter (loop over 524288 tasks)
//   grid_bar
//   phase C: psi2 on (rt, agg32_t) -> btbuf  (no bm1)
// ---------------------------------------------------------------------------
__global__ __launch_bounds__(256) void step_mid_kernel(
    const float* __restrict__ S, const float* __restrict__ rs,
    const int* __restrict__ eit, const float* __restrict__ eat,
    float* __restrict__ agg, float* __restrict__ rtbuf,
    const float* __restrict__ W2_root, const float* __restrict__ W2_nbr,
    const float* __restrict__ b2, const float* __restrict__ Wm1,
    float* __restrict__ btbuf)
{
    __shared__ union {
        struct { float Ssm[64][34]; float Rsm[64][34]; } a;
        Psi2Smem c;
    } sm;

    int tid = threadIdx.x;
    int bk = blockIdx.x;

    // ---- phase A: zero agg (1 float4 per thread) + rt GEMM ----
    {
        size_t zi = (size_t)bk * 256 + tid;
        reinterpret_cast<float4*>(agg)[zi] = make_float4(0.f, 0.f, 0.f, 0.f);
    }
    {
        int b = bk >> 4;
        int t0 = (bk & 15) * 32;
        const float* Sb = S + (size_t)b * kN * kN;
        const float* Rb = rs + (size_t)b * kN * kR;
        int t_ = tid & 15, r_ = tid >> 4;

        float a00 = 0.f, a01 = 0.f, a10 = 0.f, a11 = 0.f;
        for (int ks = 0; ks < 8; ks++) {
            __syncthreads();
            for (int i = tid; i < 64 * 32; i += 256) {
                int sr = i >> 5, c = i & 31;
                sm.a.Ssm[sr][c] = Sb[(size_t)(ks * 64 + sr) * kN + t0 + c];
                sm.a.Rsm[sr][c] = Rb[(size_t)(ks * 64 + sr) * kR + c];
            }
            __syncthreads();
            #pragma unroll 8
            for (int k = 0; k < 64; k++) {
                float2 sv = *reinterpret_cast<const float2*>(&sm.a.Ssm[k][2 * t_]);
                float2 rv = *reinterpret_cast<const float2*>(&sm.a.Rsm[k][2 * r_]);
                a00 = fmaf(sv.x, rv.x, a00);
                a01 = fmaf(sv.x, rv.y, a01);
                a10 = fmaf(sv.y, rv.x, a10);
                a11 = fmaf(sv.y, rv.y, a11);
            }
        }
        float* rt0 = rtbuf + ((size_t)b * kN + t0 + 2 * t_) * kR + 2 * r_;
        *reinterpret_cast<float2*>(rt0)       = make_float2(a00, a01);
        *reinterpret_cast<float2*>(rt0 + kR)  = make_float2(a10, a11);
    }

    grid_bar(128);

    // ---- phase B: scatter rt over t-graph edges ----
    for (int it = 0; it < 16; it++) {
        int gid = it * 32768 + bk * 256 + tid;
        int e = gid >> 3, c = gid & 7;
        int s = eit[e], d = eit[kE + e];
        float w = eat[e];
        float4 v = *reinterpret_cast<const float4*>(rtbuf + (size_t)s * 32 + c * 4);
        float* p = agg + (size_t)d * 32 + c * 4;
        asm volatile("red.global.add.v4.f32 [%0], {%1,%2,%3,%4};"
                     :: "l"(p), "f"(v.x * w), "f"(v.y * w), "f"(v.z * w), "f"(v.w * w)
                     : "memory");
    }

    grid_bar(128);

    // ---- phase C: psi2 -> btbuf ----
    psi2_body(sm.c, bk, rtbuf, agg, W2_root, W2_nbr, b2, Wm1, nullptr, btbuf, 0);
}

// ---------------------------------------------------------------------------
// K7/K9: fused consensus-MLP + S_hat add + register softmax.
//   v[s,t] = shat_in[s,t] + bm2 + sum_r relu(a_s[s,r] - b_t[t,r]) * Wm2[r]
// grid 256: 16 s-rows/block, warp per 2 rows, 2s x 4t micro over 4 t-tiles.
// ---------------------------------------------------------------------------
__global__ __launch_bounds__(256) void mlp_softmax_kernel(
    const float* __restrict__ shat_in,
    const float* __restrict__ a_s, const float* __restrict__ b_t,
    const float* __restrict__ Wm2, const float* __restrict__ bm2,
    float* __restrict__ shat_out, float* __restrict__ snorm_out,
    int writeShat)
{
    __shared__ float Asm[16][33];
    __shared__ float Bsm[128][33];
    __shared__ float w2[32];

    int b  = blockIdx.x >> 5;
    int s0 = (blockIdx.x & 31) * 16;
    int tid = threadIdx.x;
    int w = tid >> 5, lane = tid & 31;

    if (tid < 32) w2[tid] = Wm2[tid];
    const float* Ab = a_s + ((size_t)b * kN + s0) * kR;
    for (int i = tid; i < 16 * 32; i += 256) Asm[i >> 5][i & 31] = Ab[i];

    float acc[2][16];
    #pragma unroll
    for (int i = 0; i < 2; i++)
        #pragma unroll
        for (int j = 0; j < 16; j++) acc[i][j] = 0.f;

    for (int tt = 0; tt < 4; tt++) {
        __syncthreads();
        const float* Bb = b_t + ((size_t)b * kN + tt * 128) * kR;
        for (int i = tid; i < 128 * 32; i += 256) Bsm[i >> 5][i & 31] = Bb[i];
        __syncthreads();

        #pragma unroll 4
        for (int r = 0; r < 32; r++) {
            float ww = w2[r];
            float a0 = Asm[2 * w][r];
            float a1 = Asm[2 * w + 1][r];
            #pragma unroll
            for (int m = 0; m < 4; m++) {
                float bv = Bsm[lane + 32 * m][r];
                float d0 = fmaxf(a0 - bv, 0.f);
                float d1 = fmaxf(a1 - bv, 0.f);
                acc[0][tt * 4 + m] = fmaf(d0, ww, acc[0][tt * 4 + m]);
                acc[1][tt * 4 + m] = fmaf(d1, ww, acc[1][tt * 4 + m]);
            }
        }
    }

    float bm2v = bm2[0];
    #pragma unroll
    for (int si = 0; si < 2; si++) {
        int row = b * kN + s0 + 2 * w + si;
        const float* shi = shat_in + (size_t)row * kN;
        float v[16];
        #pragma unroll
        for (int j = 0; j < 16; j++) {
            int t = (j >> 2) * 128 + 32 * (j & 3) + lane;
            v[j] = shi[t] + acc[si][j] + bm2v;
        }
        float m = -3.4e38f;
        #pragma unroll
        for (int j = 0; j < 16; j++) m = fmaxf(m, v[j]);
        #pragma unroll
        for (int o = 16; o > 0; o >>= 1) m = fmaxf(m, __shfl_xor_sync(0xffffffffu, m, o));
        float s = 0.f;
        float e[16];
        #pragma unroll
        for (int j = 0; j < 16; j++) { e[j] = __expf(v[j] - m); s += e[j]; }
        #pragma unroll
        for (int o = 16; o > 0; o >>= 1) s += __shfl_xor_sync(0xffffffffu, s, o);
        float inv = 1.f / s;
        float* sn = snorm_out + (size_t)row * kN;
        #pragma unroll
        for (int j = 0; j < 16; j++) {
            int t = (j >> 2) * 128 + 32 * (j & 3) + lane;
            sn[t] = e[j] * inv;
        }
        if (writeShat) {
            float* sh = shat_out + (size_t)row * kN;
            #pragma unroll
            for (int j = 0; j < 16; j++) {
                int t = (j >> 2) * 128 + 32 * (j & 3) + lane;
                sh[t] = v[j];
            }
        }
    }
}

// ---------------------------------------------------------------------------
// Host launch (9 kernels)
// ---------------------------------------------------------------------------
extern "C" void kernel_launch(void* const* d_in, const int* in_sizes, int n_in,
                              void* d_out, int out_size)
{
    (void)in_sizes; (void)n_in; (void)out_size;
    const float* x_s     = (const float*)d_in[0];
    const int*   ei_s    = (const int*)  d_in[1];
    const float* ea_s    = (const float*)d_in[2];
    const float* x_t     = (const float*)d_in[4];
    const int*   ei_t    = (const int*)  d_in[5];
    const float* ea_t    = (const float*)d_in[6];
    const float* r_all   = (const float*)d_in[8];
    const float* W1_root = (const float*)d_in[9];
    const float* W1_nbr  = (const float*)d_in[10];
    const float* b1      = (const float*)d_in[11];
    const float* W2_root = (const float*)d_in[12];
    const float* W2_nbr  = (const float*)d_in[13];
    const float* b2      = (const float*)d_in[14];
    const float* Wm1     = (const float*)d_in[15];
    const float* bm1     = (const float*)d_in[16];
    const float* Wm2     = (const float*)d_in[17];
    const float* bm2     = (const float*)d_in[18];

    float* outS0 = (float*)d_out;
    float* outSL = outS0 + SZ_S;

    float* sc = nullptr;
    cudaGetSymbolAddress((void**)&sc, g_scratch);
    float* agg64s = sc + OFF_AGG64S;
    float* agg64t = sc + OFF_AGG64T;
    float* agg32s = sc + OFF_AGG32S;
    float* agg32t = sc + OFF_AGG32T;
    float* ys     = sc + OFF_YS;
    float* yt     = sc + OFF_YT;
    float* hs     = sc + OFF_HS;
    float* ht     = sc + OFF_HT;
    float* Shat   = sc + OFF_SHAT;
    float* Snorm  = sc + OFF_SNORM;
    float* rtbuf  = sc + OFF_RT;
    float* asbuf  = sc + OFF_AS;
    float* btbuf  = sc + OFF_BT;

    // K1: projection (both graphs) + zero atomic buffers
    proj_zero_kernel<<<dim3(256, 5), 256>>>(x_s, x_t, W1_nbr, ys, yt, sc + OFF_AGG64S);

    // K2: all input-side scatters
    scatter_all<<<dim3(4096, 4), 256>>>(ys, yt, r_all, ei_s, ei_t, ea_s, ea_t,
                                        agg64s, agg64t, agg32s);

    // K3: root GEMM -> hs, ht
    root_kernel<<<dim3(256, 2), 256>>>(x_s, x_t, W1_root, b1, agg64s, agg64t, hs, ht);

    // K4: a_s for both steps
    psi2_kernel<<<dim3(128, 2), 256>>>(r_all, agg32s, W2_root, W2_nbr, b2, Wm1, bm1, asbuf);

    // K5: S_hat0 + softmax -> Shat, outS0
    gemm_softmax_kernel<<<256, 256>>>(hs, ht, Shat, outS0);

    // ---- step 0 ----
    step_mid_kernel<<<128, 256>>>(outS0, r_all, ei_t, ea_t, agg32t, rtbuf,
                                  W2_root, W2_nbr, b2, Wm1, btbuf);
    mlp_softmax_kernel<<<256, 256>>>(Shat, asbuf, btbuf, Wm2, bm2, Shat, Snorm, 1);

    // ---- step 1 ----
    step_mid_kernel<<<128, 256>>>(Snorm, r_all + SZ_NTR, ei_t, ea_t, agg32t, rtbuf,
                                  W2_root, W2_nbr, b2, Wm1, btbuf);
    mlp_softmax_kernel<<<256, 256>>>(Shat, asbuf + SZ_NTR, btbuf, Wm2, bm2,
                                     nullptr, outSL, 0);
}

// round 4
// speedup vs baseline: 1.4234x; 1.0258x over previous
#include <cuda_runtime.h>
#include <cstdint>

// ---------------------------------------------------------------------------
// Problem constants
// ---------------------------------------------------------------------------
constexpr int kB   = 8;
constexpr int kN   = 512;
constexpr int kE   = 65536;
constexpr int kNT  = kB * kN;      // 4096
constexpr int kDH  = 64;
constexpr int kR   = 32;

constexpr size_t SZ_NTDH = (size_t)kNT * kDH;     // 262144
constexpr size_t SZ_NTR  = (size_t)kNT * kR;      // 131072
constexpr size_t SZ_S    = (size_t)kB * kN * kN;  // 2097152

// ---------------------------------------------------------------------------
// Scratch layout (buffers zeroed by proj_zero first: 786432 floats)
// ---------------------------------------------------------------------------
constexpr size_t OFF_AGG64S = 0;
constexpr size_t OFF_AGG64T = OFF_AGG64S + SZ_NTDH;
constexpr size_t OFF_AGG32S = OFF_AGG64T + SZ_NTDH;   // 2 slots (steps 0,1)
constexpr size_t OFF_AGG32T = OFF_AGG32S + 2 * SZ_NTR;
constexpr size_t OFF_YS     = OFF_AGG32T + SZ_NTR;
constexpr size_t OFF_YT     = OFF_YS     + SZ_NTDH;
constexpr size_t OFF_HS     = OFF_YT     + SZ_NTDH;
constexpr size_t OFF_HT     = OFF_HS     + SZ_NTDH;
constexpr size_t OFF_SHAT   = OFF_HT     + SZ_NTDH;
constexpr size_t OFF_SNORM  = OFF_SHAT   + SZ_S;
constexpr size_t OFF_RT     = OFF_SNORM  + SZ_S;
constexpr size_t OFF_AS     = OFF_RT     + SZ_NTR;    // 2 steps
constexpr size_t OFF_BT     = OFF_AS     + 2 * SZ_NTR;
constexpr size_t SCRATCH_TOTAL = OFF_BT + SZ_NTR;

__device__ float g_scratch[SCRATCH_TOTAL];

// Ticket grid barrier (monotonic counter: safe across launches & graph replays)
__device__ unsigned int g_bar = 0;

__device__ __forceinline__ void grid_bar(int nblk) {
    __syncthreads();
    __threadfence();
    if (threadIdx.x == 0) {
        unsigned old = atomicAdd(&g_bar, 1u);
        unsigned target = (old / nblk + 1u) * nblk;
        while (*(volatile unsigned*)&g_bar < target) { }
    }
    __syncthreads();
    __threadfence();
}

// ---------------------------------------------------------------------------
// Shared-memory layouts
// ---------------------------------------------------------------------------
struct Psi2Sm {
    float rsm[8][4][33];
    float gsm[8][4][33];
    float osm[8][4][33];
    float wr[32 * 33];
    float wn[32 * 33];
    float wm[32 * 33];
};
struct GemmSm {
    float hsS[16][64];
    float htS[128][65];
};
struct RtSm {
    float Ssm[64][34];
    float Rsm[64][34];
};
struct MlpSm {
    float Asm[16][33];
    float Bsm[128][33];
    float w2[32];
};

// ---------------------------------------------------------------------------
// psi_2 + Wm1 body (weights staged in smem by ALL 256 threads):
//   o   = relu( r @ W2_root + agg @ W2_nbr + b2 )
//   out = o @ Wm1 (+ bm1 if hasBm1)
// One call covers 32 rows (warp = 4 rows); bk in [0,128).
// ---------------------------------------------------------------------------
__device__ __forceinline__ void psi2_body(
    Psi2Sm& sm, int bk,
    const float* __restrict__ r, const float* __restrict__ agg,
    const float* __restrict__ W2_root, const float* __restrict__ W2_nbr,
    const float* __restrict__ b2, const float* __restrict__ Wm1,
    const float* __restrict__ bm1, float* __restrict__ out, int hasBm1)
{
    int tid = threadIdx.x;
    for (int i = tid; i < 1024; i += 256) {
        int k = i >> 5, c = i & 31;
        sm.wr[k * 33 + c] = W2_root[i];
        sm.wn[k * 33 + c] = W2_nbr[i];
        sm.wm[k * 33 + c] = Wm1[i];
    }

    int warp = tid >> 5, lane = tid & 31;
    int row0 = bk * 32 + warp * 4;

    #pragma unroll
    for (int rr = 0; rr < 4; rr++) {
        sm.rsm[warp][rr][lane] = r[(size_t)(row0 + rr) * 32 + lane];
        sm.gsm[warp][rr][lane] = agg[(size_t)(row0 + rr) * 32 + lane];
    }
    __syncthreads();   // weights + per-warp tiles visible

    float o[4];
    float bv = b2[lane];
    #pragma unroll
    for (int rr = 0; rr < 4; rr++) o[rr] = bv;
    #pragma unroll 8
    for (int k = 0; k < 32; k++) {
        float wr = sm.wr[k * 33 + lane];
        float wn = sm.wn[k * 33 + lane];
        #pragma unroll
        for (int rr = 0; rr < 4; rr++) {
            o[rr] = fmaf(sm.rsm[warp][rr][k], wr, o[rr]);
            o[rr] = fmaf(sm.gsm[warp][rr][k], wn, o[rr]);
        }
    }
    #pragma unroll
    for (int rr = 0; rr < 4; rr++) sm.osm[warp][rr][lane] = fmaxf(o[rr], 0.f);
    __syncwarp();

    float a[4];
    float b0 = hasBm1 ? bm1[lane] : 0.f;
    #pragma unroll
    for (int rr = 0; rr < 4; rr++) a[rr] = b0;
    #pragma unroll 8
    for (int k = 0; k < 32; k++) {
        float w = sm.wm[k * 33 + lane];
        #pragma unroll
        for (int rr = 0; rr < 4; rr++) a[rr] = fmaf(sm.osm[warp][rr][k], w, a[rr]);
    }
    #pragma unroll
    for (int rr = 0; rr < 4; rr++) out[(size_t)(row0 + rr) * 32 + lane] = a[rr];
}

// ---------------------------------------------------------------------------
// mlp + softmax body: processes 16 s-rows (block-wide), warp = 2 rows.
//   v[s,t] = shat_in[s,t] + bm2 + sum_r relu(a_s[s,r] - b_t[t,r]) * Wm2[r]
//   snorm_out = softmax_rows(v); optional shat_out = v
// ---------------------------------------------------------------------------
__device__ __forceinline__ void mlp_softmax_body(
    MlpSm& sm, int b, int s0,
    const float* __restrict__ shat_in,
    const float* __restrict__ a_s, const float* __restrict__ b_t,
    const float* __restrict__ Wm2, float bm2v,
    float* __restrict__ shat_out, float* __restrict__ snorm_out, int writeShat)
{
    int tid = threadIdx.x;
    int w = tid >> 5, lane = tid & 31;

    if (tid < 32) sm.w2[tid] = Wm2[tid];
    const float* Ab = a_s + ((size_t)b * kN + s0) * kR;
    for (int i = tid; i < 16 * 32; i += 256) sm.Asm[i >> 5][i & 31] = Ab[i];

    float acc[2][16];
    #pragma unroll
    for (int i = 0; i < 2; i++)
        #pragma unroll
        for (int j = 0; j < 16; j++) acc[i][j] = 0.f;

    for (int tt = 0; tt < 4; tt++) {
        __syncthreads();
        const float* Bb = b_t + ((size_t)b * kN + tt * 128) * kR;
        for (int i = tid; i < 128 * 32; i += 256) sm.Bsm[i >> 5][i & 31] = Bb[i];
        __syncthreads();

        #pragma unroll 4
        for (int r = 0; r < 32; r++) {
            float ww = sm.w2[r];
            float a0 = sm.Asm[2 * w][r];
            float a1 = sm.Asm[2 * w + 1][r];
            #pragma unroll
            for (int m = 0; m < 4; m++) {
                float bv = sm.Bsm[lane + 32 * m][r];
                float d0 = fmaxf(a0 - bv, 0.f);
                float d1 = fmaxf(a1 - bv, 0.f);
                acc[0][tt * 4 + m] = fmaf(d0, ww, acc[0][tt * 4 + m]);
                acc[1][tt * 4 + m] = fmaf(d1, ww, acc[1][tt * 4 + m]);
            }
        }
    }

    #pragma unroll
    for (int si = 0; si < 2; si++) {
        int row = b * kN + s0 + 2 * w + si;
        const float* shi = shat_in + (size_t)row * kN;
        float v[16];
        #pragma unroll
        for (int j = 0; j < 16; j++) {
            int t = (j >> 2) * 128 + 32 * (j & 3) + lane;
            v[j] = shi[t] + acc[si][j] + bm2v;
        }
        float m = -3.4e38f;
        #pragma unroll
        for (int j = 0; j < 16; j++) m = fmaxf(m, v[j]);
        #pragma unroll
        for (int o = 16; o > 0; o >>= 1) m = fmaxf(m, __shfl_xor_sync(0xffffffffu, m, o));
        float s = 0.f;
        float e[16];
        #pragma unroll
        for (int j = 0; j < 16; j++) { e[j] = __expf(v[j] - m); s += e[j]; }
        #pragma unroll
        for (int o = 16; o > 0; o >>= 1) s += __shfl_xor_sync(0xffffffffu, s, o);
        float inv = 1.f / s;
        float* sn = snorm_out + (size_t)row * kN;
        #pragma unroll
        for (int j = 0; j < 16; j++) {
            int t = (j >> 2) * 128 + 32 * (j & 3) + lane;
            sn[t] = e[j] * inv;
        }
        if (writeShat) {
            float* sh = shat_out + (size_t)row * kN;
            #pragma unroll
            for (int j = 0; j < 16; j++) {
                int t = (j >> 2) * 128 + 32 * (j & 3) + lane;
                sh[t] = v[j];
            }
        }
    }
}

// ---------------------------------------------------------------------------
// K1: projection (x @ W1_nbr, both graphs) + zero atomic buffers. grid (256,5)
// ---------------------------------------------------------------------------
__global__ __launch_bounds__(256) void proj_zero_kernel(
    const float* __restrict__ x_s, const float* __restrict__ x_t,
    const float* __restrict__ W, float* __restrict__ ys, float* __restrict__ yt,
    float* __restrict__ zerobase)
{
    int y = blockIdx.y;
    int tid = threadIdx.x;
    if (y >= 2) {
        size_t i = (size_t)(y - 2) * 65536 + (size_t)blockIdx.x * 256 + tid;
        reinterpret_cast<float4*>(zerobase)[i] = make_float4(0.f, 0.f, 0.f, 0.f);
        return;
    }
    const float* A = y == 0 ? x_s : x_t;
    float*       out = y == 0 ? ys : yt;

    __shared__ float As[16][128];
    int row0 = blockIdx.x * 16;
    for (int i = tid; i < 16 * 128; i += 256)
        As[i >> 7][i & 127] = A[(size_t)row0 * 128 + i];
    __syncthreads();

    int j = tid & 63, g = tid >> 6;
    float acc[4] = {0.f, 0.f, 0.f, 0.f};
    #pragma unroll 4
    for (int k = 0; k < 128; k++) {
        float w = __ldg(&W[k * 64 + j]);
        #pragma unroll
        for (int rr = 0; rr < 4; rr++)
            acc[rr] = fmaf(As[g * 4 + rr][k], w, acc[rr]);
    }
    #pragma unroll
    for (int rr = 0; rr < 4; rr++)
        out[(size_t)(row0 + g * 4 + rr) * 64 + j] = acc[rr];
}

// ---------------------------------------------------------------------------
// K2: all input-side scatters. grid (4096, 4), block 256.
// ---------------------------------------------------------------------------
__global__ __launch_bounds__(256) void scatter_all(
    const float* __restrict__ ys, const float* __restrict__ yt,
    const float* __restrict__ r_all,
    const int* __restrict__ eis, const int* __restrict__ eit,
    const float* __restrict__ eas, const float* __restrict__ eat,
    float* __restrict__ agg64s, float* __restrict__ agg64t,
    float* __restrict__ agg32s)
{
    int y = blockIdx.y;
    if (y < 2) {
        const float* src_y = y == 0 ? ys : yt;
        const int*   ei    = y == 0 ? eis : eit;
        const float* ea    = y == 0 ? eas : eat;
        float*       agg   = y == 0 ? agg64s : agg64t;
        int tid = blockIdx.x * 256 + threadIdx.x;
        int e = tid >> 4, c = tid & 15;
        int s = ei[e], d = ei[kE + e];
        float w = ea[e];
        float4 v = *reinterpret_cast<const float4*>(src_y + (size_t)s * 64 + c * 4);
        float* p = agg + (size_t)d * 64 + c * 4;
        asm volatile("red.global.add.v4.f32 [%0], {%1,%2,%3,%4};"
                     :: "l"(p), "f"(v.x * w), "f"(v.y * w), "f"(v.z * w), "f"(v.w * w)
                     : "memory");
    } else {
        if (blockIdx.x >= 2048) return;
        int step = y - 2;
        const float* src_y = r_all + (size_t)step * SZ_NTR;
        float*       agg   = agg32s + (size_t)step * SZ_NTR;
        int tid = blockIdx.x * 256 + threadIdx.x;
        int e = tid >> 3, c = tid & 7;
        int s = eis[e], d = eis[kE + e];
        float w = eas[e];
        float4 v = *reinterpret_cast<const float4*>(src_y + (size_t)s * 32 + c * 4);
        float* p = agg + (size_t)d * 32 + c * 4;
        asm volatile("red.global.add.v4.f32 [%0], {%1,%2,%3,%4};"
                     :: "l"(p), "f"(v.x * w), "f"(v.y * w), "f"(v.z * w), "f"(v.w * w)
                     : "memory");
    }
}

// ---------------------------------------------------------------------------
// K3: root GEMM: h = relu(x @ W1_root + b1 + agg), both graphs. grid (256,2)
// ---------------------------------------------------------------------------
__global__ __launch_bounds__(256) void root_kernel(
    const float* __restrict__ x_s, const float* __restrict__ x_t,
    const float* __restrict__ W, const float* __restrict__ bias,
    const float* __restrict__ agg_s, const float* __restrict__ agg_t,
    float* __restrict__ hs, float* __restrict__ ht)
{
    int y = blockIdx.y;
    const float* A   = y == 0 ? x_s   : x_t;
    const float* add = y == 0 ? agg_s : agg_t;
    float*       out = y == 0 ? hs    : ht;

    __shared__ float As[16][128];
    int tid = threadIdx.x;
    int row0 = blockIdx.x * 16;
    for (int i = tid; i < 16 * 128; i += 256)
        As[i >> 7][i & 127] = A[(size_t)row0 * 128 + i];
    __syncthreads();

    int j = tid & 63, g = tid >> 6;
    float bv = bias[j];
    float acc[4] = {bv, bv, bv, bv};
    #pragma unroll 4
    for (int k = 0; k < 128; k++) {
        float w = __ldg(&W[k * 64 + j]);
        #pragma unroll
        for (int rr = 0; rr < 4; rr++)
            acc[rr] = fmaf(As[g * 4 + rr][k], w, acc[rr]);
    }
    #pragma unroll
    for (int rr = 0; rr < 4; rr++) {
        size_t idx = (size_t)(row0 + g * 4 + rr) * 64 + j;
        out[idx] = fmaxf(acc[rr] + add[idx], 0.f);
    }
}

// ---------------------------------------------------------------------------
// K4: gemm_softmax (blocks 0..255) + psi2 a_s precompute (blocks 256..511)
// ---------------------------------------------------------------------------
__global__ __launch_bounds__(256) void gemm_psi2_kernel(
    const float* __restrict__ hs, const float* __restrict__ ht,
    float* __restrict__ shat, float* __restrict__ snorm,
    const float* __restrict__ r_all, const float* __restrict__ agg32s,
    const float* __restrict__ W2_root, const float* __restrict__ W2_nbr,
    const float* __restrict__ b2, const float* __restrict__ Wm1,
    const float* __restrict__ bm1, float* __restrict__ asbuf)
{
    __shared__ union { GemmSm g; Psi2Sm p; } sm;
    int blk = blockIdx.x;
    int tid = threadIdx.x;

    if (blk >= 256) {
        int bidx = blk - 256;
        int step = bidx >> 7;
        psi2_body(sm.p, bidx & 127,
                  r_all + (size_t)step * SZ_NTR, agg32s + (size_t)step * SZ_NTR,
                  W2_root, W2_nbr, b2, Wm1, bm1,
                  asbuf + (size_t)step * SZ_NTR, 1);
        return;
    }

    int b  = blk >> 5;
    int s0 = (blk & 31) * 16;
    int w = tid >> 5, lane = tid & 31;

    const float* hsb = hs + ((size_t)b * kN + s0) * kDH;
    for (int i = tid; i < 16 * 64; i += 256) sm.g.hsS[i >> 6][i & 63] = hsb[i];

    float acc[2][16];
    #pragma unroll
    for (int i = 0; i < 2; i++)
        #pragma unroll
        for (int j = 0; j < 16; j++) acc[i][j] = 0.f;

    for (int tt = 0; tt < 4; tt++) {
        __syncthreads();
        const float* htb = ht + ((size_t)b * kN + tt * 128) * kDH;
        for (int i = tid; i < 128 * 64; i += 256) sm.g.htS[i >> 6][i & 63] = htb[i];
        __syncthreads();

        #pragma unroll 4
        for (int k = 0; k < 64; k++) {
            float a0 = sm.g.hsS[2 * w][k];
            float a1 = sm.g.hsS[2 * w + 1][k];
            #pragma unroll
            for (int m = 0; m < 4; m++) {
                float hv = sm.g.htS[lane + 32 * m][k];
                acc[0][tt * 4 + m] = fmaf(a0, hv, acc[0][tt * 4 + m]);
                acc[1][tt * 4 + m] = fmaf(a1, hv, acc[1][tt * 4 + m]);
            }
        }
    }

    #pragma unroll
    for (int si = 0; si < 2; si++) {
        int row = b * kN + s0 + 2 * w + si;
        float m = -3.4e38f;
        #pragma unroll
        for (int j = 0; j < 16; j++) m = fmaxf(m, acc[si][j]);
        #pragma unroll
        for (int o = 16; o > 0; o >>= 1) m = fmaxf(m, __shfl_xor_sync(0xffffffffu, m, o));
        float s = 0.f;
        float e[16];
        #pragma unroll
        for (int j = 0; j < 16; j++) { e[j] = __expf(acc[si][j] - m); s += e[j]; }
        #pragma unroll
        for (int o = 16; o > 0; o >>= 1) s += __shfl_xor_sync(0xffffffffu, s, o);
        float inv = 1.f / s;
        float* sh = shat + (size_t)row * kN;
        float* sn = snorm + (size_t)row * kN;
        #pragma unroll
        for (int j = 0; j < 16; j++) {
            int t = (j >> 2) * 128 + 32 * (j & 3) + lane;
            sh[t] = acc[si][j];
            sn[t] = e[j] * inv;
        }
    }
}

// ---------------------------------------------------------------------------
// K5/K6: ONE persistent kernel per consensus step (grid 128, block 256):
//   A: zero agg32_t + rt = S^T @ r_s       | bar
//   B: t-graph raw-r scatter               | bar
//   C: psi2(rt, agg) -> btbuf              | bar
//   D: mlp + S_hat add + softmax (32 s-rows/block, 2 halves)
// ---------------------------------------------------------------------------
__global__ __launch_bounds__(256) void step_kernel(
    const float* __restrict__ S, const float* __restrict__ rs,
    const int* __restrict__ eit, const float* __restrict__ eat,
    float* __restrict__ agg, float* __restrict__ rtbuf,
    const float* __restrict__ W2_root, const float* __restrict__ W2_nbr,
    const float* __restrict__ b2, const float* __restrict__ Wm1,
    float* __restrict__ btbuf,
    const float* __restrict__ shat_in, const float* __restrict__ a_s,
    const float* __restrict__ Wm2, const float* __restrict__ bm2,
    float* __restrict__ shat_out, float* __restrict__ snorm_out, int writeShat)
{
    __shared__ union { RtSm a; Psi2Sm c; MlpSm d; } sm;

    int tid = threadIdx.x;
    int bk = blockIdx.x;

    // ---- phase A: zero agg + rt GEMM ----
    {
        size_t zi = (size_t)bk * 256 + tid;
        reinterpret_cast<float4*>(agg)[zi] = make_float4(0.f, 0.f, 0.f, 0.f);
    }
    {
        int b = bk >> 4;
        int t0 = (bk & 15) * 32;
        const float* Sb = S + (size_t)b * kN * kN;
        const float* Rb = rs + (size_t)b * kN * kR;
        int t_ = tid & 15, r_ = tid >> 4;

        float a00 = 0.f, a01 = 0.f, a10 = 0.f, a11 = 0.f;
        for (int ks = 0; ks < 8; ks++) {
            __syncthreads();
            for (int i = tid; i < 64 * 32; i += 256) {
                int sr = i >> 5, c = i & 31;
                sm.a.Ssm[sr][c] = Sb[(size_t)(ks * 64 + sr) * kN + t0 + c];
                sm.a.Rsm[sr][c] = Rb[(size_t)(ks * 64 + sr) * kR + c];
            }
            __syncthreads();
            #pragma unroll 8
            for (int k = 0; k < 64; k++) {
                float2 sv = *reinterpret_cast<const float2*>(&sm.a.Ssm[k][2 * t_]);
                float2 rv = *reinterpret_cast<const float2*>(&sm.a.Rsm[k][2 * r_]);
                a00 = fmaf(sv.x, rv.x, a00);
                a01 = fmaf(sv.x, rv.y, a01);
                a10 = fmaf(sv.y, rv.x, a10);
                a11 = fmaf(sv.y, rv.y, a11);
            }
        }
        float* rt0 = rtbuf + ((size_t)b * kN + t0 + 2 * t_) * kR + 2 * r_;
        *reinterpret_cast<float2*>(rt0)      = make_float2(a00, a01);
        *reinterpret_cast<float2*>(rt0 + kR) = make_float2(a10, a11);
    }

    grid_bar(128);

    // ---- phase B: scatter rt over t-graph edges ----
    for (int it = 0; it < 16; it++) {
        int gid = it * 32768 + bk * 256 + tid;
        int e = gid >> 3, c = gid & 7;
        int s = eit[e], d = eit[kE + e];
        float w = eat[e];
        float4 v = *reinterpret_cast<const float4*>(rtbuf + (size_t)s * 32 + c * 4);
        float* p = agg + (size_t)d * 32 + c * 4;
        asm volatile("red.global.add.v4.f32 [%0], {%1,%2,%3,%4};"
                     :: "l"(p), "f"(v.x * w), "f"(v.y * w), "f"(v.z * w), "f"(v.w * w)
                     : "memory");
    }

    grid_bar(128);

    // ---- phase C: psi2 -> btbuf ----
    psi2_body(sm.c, bk, rtbuf, agg, W2_root, W2_nbr, b2, Wm1, nullptr, btbuf, 0);

    grid_bar(128);

    // ---- phase D: mlp + softmax, 32 s-rows per block ----
    {
        int b = bk >> 4;
        int sbase = (bk & 15) * 32;
        float bm2v = bm2[0];
        for (int half = 0; half < 2; half++) {
            __syncthreads();
            mlp_softmax_body(sm.d, b, sbase + half * 16, shat_in, a_s, btbuf,
                             Wm2, bm2v, shat_out, snorm_out, writeShat);
        }
    }
}

// ---------------------------------------------------------------------------
// Host launch (6 kernels)
// ---------------------------------------------------------------------------
extern "C" void kernel_launch(void* const* d_in, const int* in_sizes, int n_in,
                              void* d_out, int out_size)
{
    (void)in_sizes; (void)n_in; (void)out_size;
    const float* x_s     = (const float*)d_in[0];
    const int*   ei_s    = (const int*)  d_in[1];
    const float* ea_s    = (const float*)d_in[2];
    const float* x_t     = (const float*)d_in[4];
    const int*   ei_t    = (const int*)  d_in[5];
    const float* ea_t    = (const float*)d_in[6];
    const float* r_all   = (const float*)d_in[8];
    const float* W1_root = (const float*)d_in[9];
    const float* W1_nbr  = (const float*)d_in[10];
    const float* b1      = (const float*)d_in[11];
    const float* W2_root = (const float*)d_in[12];
    const float* W2_nbr  = (const float*)d_in[13];
    const float* b2      = (const float*)d_in[14];
    const float* Wm1     = (const float*)d_in[15];
    const float* bm1     = (const float*)d_in[16];
    const float* Wm2     = (const float*)d_in[17];
    const float* bm2     = (const float*)d_in[18];

    float* outS0 = (float*)d_out;
    float* outSL = outS0 + SZ_S;

    float* sc = nullptr;
    cudaGetSymbolAddress((void**)&sc, g_scratch);
    float* agg64s = sc + OFF_AGG64S;
    float* agg64t = sc + OFF_AGG64T;
    float* agg32s = sc + OFF_AGG32S;
    float* agg32t = sc + OFF_AGG32T;
    float* ys     = sc + OFF_YS;
    float* yt     = sc + OFF_YT;
    float* hs     = sc + OFF_HS;
    float* ht     = sc + OFF_HT;
    float* Shat   = sc + OFF_SHAT;
    float* Snorm  = sc + OFF_SNORM;
    float* rtbuf  = sc + OFF_RT;
    float* asbuf  = sc + OFF_AS;
    float* btbuf  = sc + OFF_BT;

    // K1: projection (both graphs) + zero atomic buffers
    proj_zero_kernel<<<dim3(256, 5), 256>>>(x_s, x_t, W1_nbr, ys, yt, sc + OFF_AGG64S);

    // K2: all input-side scatters
    scatter_all<<<dim3(4096, 4), 256>>>(ys, yt, r_all, ei_s, ei_t, ea_s, ea_t,
                                        agg64s, agg64t, agg32s);

    // K3: root GEMM -> hs, ht
    root_kernel<<<dim3(256, 2), 256>>>(x_s, x_t, W1_root, b1, agg64s, agg64t, hs, ht);

    // K4: S_hat0 GEMM+softmax (-> Shat, outS0)  +  a_s precompute (both steps)
    gemm_psi2_kernel<<<512, 256>>>(hs, ht, Shat, outS0, r_all, agg32s,
                                   W2_root, W2_nbr, b2, Wm1, bm1, asbuf);

    // K5: consensus step 0 (fused chain)
    step_kernel<<<128, 256>>>(outS0, r_all, ei_t, ea_t, agg32t, rtbuf,
                              W2_root, W2_nbr, b2, Wm1, btbuf,
                              Shat, asbuf, Wm2, bm2, Shat, Snorm, 1);

    // K6: consensus step 1 (fused chain)
    step_kernel<<<128, 256>>>(Snorm, r_all + SZ_NTR, ei_t, ea_t, agg32t, rtbuf,
                              W2_root, W2_nbr, b2, Wm1, btbuf,
                              Shat, asbuf + SZ_NTR, Wm2, bm2, nullptr, outSL, 0);
}

// round 5
// speedup vs baseline: 1.4976x; 1.0521x over previous
#include <cuda_runtime.h>
#include <cstdint>

// ---------------------------------------------------------------------------
// Problem constants
// ---------------------------------------------------------------------------
constexpr int kB   = 8;
constexpr int kN   = 512;
constexpr int kE   = 65536;
constexpr int kNT  = kB * kN;      // 4096
constexpr int kDH  = 64;
constexpr int kR   = 32;

constexpr size_t SZ_NTDH = (size_t)kNT * kDH;     // 262144
constexpr size_t SZ_NTR  = (size_t)kNT * kR;      // 131072
constexpr size_t SZ_S    = (size_t)kB * kN * kN;  // 2097152

// ---------------------------------------------------------------------------
// Scratch layout (buffers zeroed by proj_zero first: 786432 floats)
// ---------------------------------------------------------------------------
constexpr size_t OFF_AGG64S = 0;
constexpr size_t OFF_AGG64T = OFF_AGG64S + SZ_NTDH;
constexpr size_t OFF_AGG32S = OFF_AGG64T + SZ_NTDH;   // 2 slots (steps 0,1)
constexpr size_t OFF_AGG32T = OFF_AGG32S + 2 * SZ_NTR;
constexpr size_t OFF_YS     = OFF_AGG32T + SZ_NTR;
constexpr size_t OFF_YT     = OFF_YS     + SZ_NTDH;
constexpr size_t OFF_HS     = OFF_YT     + SZ_NTDH;
constexpr size_t OFF_HT     = OFF_HS     + SZ_NTDH;
constexpr size_t OFF_SHAT   = OFF_HT     + SZ_NTDH;
constexpr size_t OFF_SNORM  = OFF_SHAT   + SZ_S;
constexpr size_t OFF_RT     = OFF_SNORM  + SZ_S;
constexpr size_t OFF_AS     = OFF_RT     + SZ_NTR;    // 2 steps
constexpr size_t OFF_BT     = OFF_AS     + 2 * SZ_NTR;
constexpr size_t SCRATCH_TOTAL = OFF_BT + SZ_NTR;

__device__ float g_scratch[SCRATCH_TOTAL];

// Ticket grid barrier (monotonic counter: safe across launches & graph replays)
__device__ unsigned int g_bar = 0;

__device__ __forceinline__ void grid_bar(int nblk) {
    __syncthreads();
    __threadfence();
    if (threadIdx.x == 0) {
        unsigned old = atomicAdd(&g_bar, 1u);
        unsigned target = (old / nblk + 1u) * nblk;
        while (*(volatile unsigned*)&g_bar < target) { }
    }
    __syncthreads();
    __threadfence();
}

// ---------------------------------------------------------------------------
// Shared-memory layouts
// ---------------------------------------------------------------------------
struct Psi2Sm {
    float rsm[8][4][33];
    float gsm[8][4][33];
    float osm[8][4][33];
    float wr[32 * 33];
    float wn[32 * 33];
    float wm[32 * 33];
};
struct RtSm {
    float Ssm[64][17];
    float Rsm[64][34];
};
struct MlpSm {
    float Asm[16][33];
    float Bsm[128][33];
    float w2[32];
};

// ---------------------------------------------------------------------------
// psi_2 + Wm1 body (weights staged to smem by all 256 threads):
//   o   = relu( r @ W2_root + agg @ W2_nbr + b2 )
//   out = o @ Wm1 (+ bm1 if hasBm1)
// Covers 8 warps * RPW rows starting at row_base.
// ---------------------------------------------------------------------------
template<int RPW>
__device__ __forceinline__ void psi2_body(
    Psi2Sm& sm, int row_base,
    const float* __restrict__ r, const float* __restrict__ agg,
    const float* __restrict__ W2_root, const float* __restrict__ W2_nbr,
    const float* __restrict__ b2, const float* __restrict__ Wm1,
    const float* __restrict__ bm1, float* __restrict__ out, int hasBm1)
{
    int tid = threadIdx.x;
    for (int i = tid; i < 1024; i += 256) {
        int k = i >> 5, c = i & 31;
        sm.wr[k * 33 + c] = W2_root[i];
        sm.wn[k * 33 + c] = W2_nbr[i];
        sm.wm[k * 33 + c] = Wm1[i];
    }

    int warp = tid >> 5, lane = tid & 31;
    int row0 = row_base + warp * RPW;

    #pragma unroll
    for (int rr = 0; rr < RPW; rr++) {
        sm.rsm[warp][rr][lane] = r[(size_t)(row0 + rr) * 32 + lane];
        sm.gsm[warp][rr][lane] = agg[(size_t)(row0 + rr) * 32 + lane];
    }
    __syncthreads();

    float o[RPW];
    float bv = b2[lane];
    #pragma unroll
    for (int rr = 0; rr < RPW; rr++) o[rr] = bv;
    #pragma unroll 8
    for (int k = 0; k < 32; k++) {
        float wr = sm.wr[k * 33 + lane];
        float wn = sm.wn[k * 33 + lane];
        #pragma unroll
        for (int rr = 0; rr < RPW; rr++) {
            o[rr] = fmaf(sm.rsm[warp][rr][k], wr, o[rr]);
            o[rr] = fmaf(sm.gsm[warp][rr][k], wn, o[rr]);
        }
    }
    #pragma unroll
    for (int rr = 0; rr < RPW; rr++) sm.osm[warp][rr][lane] = fmaxf(o[rr], 0.f);
    __syncwarp();

    float a[RPW];
    float b0 = hasBm1 ? bm1[lane] : 0.f;
    #pragma unroll
    for (int rr = 0; rr < RPW; rr++) a[rr] = b0;
    #pragma unroll 8
    for (int k = 0; k < 32; k++) {
        float w = sm.wm[k * 33 + lane];
        #pragma unroll
        for (int rr = 0; rr < RPW; rr++) a[rr] = fmaf(sm.osm[warp][rr][k], w, a[rr]);
    }
    #pragma unroll
    for (int rr = 0; rr < RPW; rr++) out[(size_t)(row0 + rr) * 32 + lane] = a[rr];
}

// ---------------------------------------------------------------------------
// mlp + softmax body: 16 s-rows (block-wide), warp = 2 rows.
//   v[s,t] = shat_in[s,t] + bm2 + sum_r relu(a_s[s,r] - b_t[t,r]) * Wm2[r]
// ---------------------------------------------------------------------------
__device__ __forceinline__ void mlp_softmax_body(
    MlpSm& sm, int b, int s0,
    const float* __restrict__ shat_in,
    const float* __restrict__ a_s, const float* __restrict__ b_t,
    const float* __restrict__ Wm2, float bm2v,
    float* __restrict__ shat_out, float* __restrict__ snorm_out, int writeShat)
{
    int tid = threadIdx.x;
    int w = tid >> 5, lane = tid & 31;

    if (tid < 32) sm.w2[tid] = Wm2[tid];
    const float* Ab = a_s + ((size_t)b * kN + s0) * kR;
    for (int i = tid; i < 16 * 32; i += 256) sm.Asm[i >> 5][i & 31] = Ab[i];

    float acc[2][16];
    #pragma unroll
    for (int i = 0; i < 2; i++)
        #pragma unroll
        for (int j = 0; j < 16; j++) acc[i][j] = 0.f;

    for (int tt = 0; tt < 4; tt++) {
        __syncthreads();
        const float* Bb = b_t + ((size_t)b * kN + tt * 128) * kR;
        for (int i = tid; i < 128 * 32; i += 256) sm.Bsm[i >> 5][i & 31] = Bb[i];
        __syncthreads();

        #pragma unroll 4
        for (int r = 0; r < 32; r++) {
            float ww = sm.w2[r];
            float a0 = sm.Asm[2 * w][r];
            float a1 = sm.Asm[2 * w + 1][r];
            #pragma unroll
            for (int m = 0; m < 4; m++) {
                float bv = sm.Bsm[lane + 32 * m][r];
                float d0 = fmaxf(a0 - bv, 0.f);
                float d1 = fmaxf(a1 - bv, 0.f);
                acc[0][tt * 4 + m] = fmaf(d0, ww, acc[0][tt * 4 + m]);
                acc[1][tt * 4 + m] = fmaf(d1, ww, acc[1][tt * 4 + m]);
            }
        }
    }

    #pragma unroll
    for (int si = 0; si < 2; si++) {
        int row = b * kN + s0 + 2 * w + si;
        const float* shi = shat_in + (size_t)row * kN;
        float v[16];
        #pragma unroll
        for (int j = 0; j < 16; j++) {
            int t = (j >> 2) * 128 + 32 * (j & 3) + lane;
            v[j] = shi[t] + acc[si][j] + bm2v;
        }
        float m = -3.4e38f;
        #pragma unroll
        for (int j = 0; j < 16; j++) m = fmaxf(m, v[j]);
        #pragma unroll
        for (int o = 16; o > 0; o >>= 1) m = fmaxf(m, __shfl_xor_sync(0xffffffffu, m, o));
        float s = 0.f;
        float e[16];
        #pragma unroll
        for (int j = 0; j < 16; j++) { e[j] = __expf(v[j] - m); s += e[j]; }
        #pragma unroll
        for (int o = 16; o > 0; o >>= 1) s += __shfl_xor_sync(0xffffffffu, s, o);
        float inv = 1.f / s;
        float* sn = snorm_out + (size_t)row * kN;
        #pragma unroll
        for (int j = 0; j < 16; j++) {
            int t = (j >> 2) * 128 + 32 * (j & 3) + lane;
            sn[t] = e[j] * inv;
        }
        if (writeShat) {
            float* sh = shat_out + (size_t)row * kN;
            #pragma unroll
            for (int j = 0; j < 16; j++) {
                int t = (j >> 2) * 128 + 32 * (j & 3) + lane;
                sh[t] = v[j];
            }
        }
    }
}

// ---------------------------------------------------------------------------
// K1: projection (x @ W1_nbr, both graphs) + zero atomic buffers. grid (256,5)
// ---------------------------------------------------------------------------
__global__ __launch_bounds__(256) void proj_zero_kernel(
    const float* __restrict__ x_s, const float* __restrict__ x_t,
    const float* __restrict__ W, float* __restrict__ ys, float* __restrict__ yt,
    float* __restrict__ zerobase)
{
    int y = blockIdx.y;
    int tid = threadIdx.x;
    if (y >= 2) {
        size_t i = (size_t)(y - 2) * 65536 + (size_t)blockIdx.x * 256 + tid;
        reinterpret_cast<float4*>(zerobase)[i] = make_float4(0.f, 0.f, 0.f, 0.f);
        return;
    }
    const float* A = y == 0 ? x_s : x_t;
    float*       out = y == 0 ? ys : yt;

    __shared__ float As[16][128];
    int row0 = blockIdx.x * 16;
    for (int i = tid; i < 16 * 128; i += 256)
        As[i >> 7][i & 127] = A[(size_t)row0 * 128 + i];
    __syncthreads();

    int j = tid & 63, g = tid >> 6;
    float acc[4] = {0.f, 0.f, 0.f, 0.f};
    #pragma unroll 4
    for (int k = 0; k < 128; k++) {
        float w = __ldg(&W[k * 64 + j]);
        #pragma unroll
        for (int rr = 0; rr < 4; rr++)
            acc[rr] = fmaf(As[g * 4 + rr][k], w, acc[rr]);
    }
    #pragma unroll
    for (int rr = 0; rr < 4; rr++)
        out[(size_t)(row0 + g * 4 + rr) * 64 + j] = acc[rr];
}

// ---------------------------------------------------------------------------
// K2: all input-side scatters. grid (4096, 4), block 256.
// ---------------------------------------------------------------------------
__global__ __launch_bounds__(256) void scatter_all(
    const float* __restrict__ ys, const float* __restrict__ yt,
    const float* __restrict__ r_all,
    const int* __restrict__ eis, const int* __restrict__ eit,
    const float* __restrict__ eas, const float* __restrict__ eat,
    float* __restrict__ agg64s, float* __restrict__ agg64t,
    float* __restrict__ agg32s)
{
    int y = blockIdx.y;
    if (y < 2) {
        const float* src_y = y == 0 ? ys : yt;
        const int*   ei    = y == 0 ? eis : eit;
        const float* ea    = y == 0 ? eas : eat;
        float*       agg   = y == 0 ? agg64s : agg64t;
        int tid = blockIdx.x * 256 + threadIdx.x;
        int e = tid >> 4, c = tid & 15;
        int s = ei[e], d = ei[kE + e];
        float w = ea[e];
        float4 v = *reinterpret_cast<const float4*>(src_y + (size_t)s * 64 + c * 4);
        float* p = agg + (size_t)d * 64 + c * 4;
        asm volatile("red.global.add.v4.f32 [%0], {%1,%2,%3,%4};"
                     :: "l"(p), "f"(v.x * w), "f"(v.y * w), "f"(v.z * w), "f"(v.w * w)
                     : "memory");
    } else {
        if (blockIdx.x >= 2048) return;
        int step = y - 2;
        const float* src_y = r_all + (size_t)step * SZ_NTR;
        float*       agg   = agg32s + (size_t)step * SZ_NTR;
        int tid = blockIdx.x * 256 + threadIdx.x;
        int e = tid >> 3, c = tid & 7;
        int s = eis[e], d = eis[kE + e];
        float w = eas[e];
        float4 v = *reinterpret_cast<const float4*>(src_y + (size_t)s * 32 + c * 4);
        float* p = agg + (size_t)d * 32 + c * 4;
        asm volatile("red.global.add.v4.f32 [%0], {%1,%2,%3,%4};"
                     :: "l"(p), "f"(v.x * w), "f"(v.y * w), "f"(v.z * w), "f"(v.w * w)
                     : "memory");
    }
}

// ---------------------------------------------------------------------------
// K3: root GEMM (blocks 0..511) + psi2 a_s precompute (blocks 512..767).
//   root: h = relu(x @ W1_root + b1 + agg64), 16 rows/block
//   psi2: a_s[step] = psi2(r_step, agg32s[step]) @ Wm1 + bm1, 32 rows/block
// ---------------------------------------------------------------------------
__global__ __launch_bounds__(256) void root_psi2_kernel(
    const float* __restrict__ x_s, const float* __restrict__ x_t,
    const float* __restrict__ W, const float* __restrict__ bias,
    const float* __restrict__ agg_s, const float* __restrict__ agg_t,
    float* __restrict__ hs, float* __restrict__ ht,
    const float* __restrict__ r_all, const float* __restrict__ agg32s,
    const float* __restrict__ W2_root, const float* __restrict__ W2_nbr,
    const float* __restrict__ b2, const float* __restrict__ Wm1,
    const float* __restrict__ bm1, float* __restrict__ asbuf)
{
    __shared__ union { float As[16][128]; Psi2Sm p; } sm;
    int bk = blockIdx.x;
    int tid = threadIdx.x;

    if (bk >= 512) {
        int idx = bk - 512;
        int step = idx >> 7;
        psi2_body<4>(sm.p, (idx & 127) * 32,
                     r_all + (size_t)step * SZ_NTR, agg32s + (size_t)step * SZ_NTR,
                     W2_root, W2_nbr, b2, Wm1, bm1,
                     asbuf + (size_t)step * SZ_NTR, 1);
        return;
    }

    int y = bk >> 8;
    const float* A   = y == 0 ? x_s   : x_t;
    const float* add = y == 0 ? agg_s : agg_t;
    float*       out = y == 0 ? hs    : ht;

    int row0 = (bk & 255) * 16;
    for (int i = tid; i < 16 * 128; i += 256)
        sm.As[i >> 7][i & 127] = A[(size_t)row0 * 128 + i];
    __syncthreads();

    int j = tid & 63, g = tid >> 6;
    float bv = bias[j];
    float acc[4] = {bv, bv, bv, bv};
    #pragma unroll 4
    for (int k = 0; k < 128; k++) {
        float w = __ldg(&W[k * 64 + j]);
        #pragma unroll
        for (int rr = 0; rr < 4; rr++)
            acc[rr] = fmaf(sm.As[g * 4 + rr][k], w, acc[rr]);
    }
    #pragma unroll
    for (int rr = 0; rr < 4; rr++) {
        size_t idx = (size_t)(row0 + g * 4 + rr) * 64 + j;
        out[idx] = fmaxf(acc[rr] + add[idx], 0.f);
    }
}

// ---------------------------------------------------------------------------
// K4: fused S_hat0 GEMM-NT + register softmax (standalone again).
// grid 256: 16 s-rows/block, warp = 2 rows, 2s x 16t accumulators.
// ---------------------------------------------------------------------------
__global__ __launch_bounds__(256) void gemm_softmax_kernel(
    const float* __restrict__ hs, const float* __restrict__ ht,
    float* __restrict__ shat, float* __restrict__ snorm)
{
    __shared__ float hsS[16][64];
    __shared__ float htS[128][65];

    int b  = blockIdx.x >> 5;
    int s0 = (blockIdx.x & 31) * 16;
    int tid = threadIdx.x;
    int w = tid >> 5, lane = tid & 31;

    const float* hsb = hs + ((size_t)b * kN + s0) * kDH;
    for (int i = tid; i < 16 * 64; i += 256) hsS[i >> 6][i & 63] = hsb[i];

    float acc[2][16];
    #pragma unroll
    for (int i = 0; i < 2; i++)
        #pragma unroll
        for (int j = 0; j < 16; j++) acc[i][j] = 0.f;

    for (int tt = 0; tt < 4; tt++) {
        __syncthreads();
        const float* htb = ht + ((size_t)b * kN + tt * 128) * kDH;
        for (int i = tid; i < 128 * 64; i += 256) htS[i >> 6][i & 63] = htb[i];
        __syncthreads();

        #pragma unroll 4
        for (int k = 0; k < 64; k++) {
            float a0 = hsS[2 * w][k];
            float a1 = hsS[2 * w + 1][k];
            #pragma unroll
            for (int m = 0; m < 4; m++) {
                float hv = htS[lane + 32 * m][k];
                acc[0][tt * 4 + m] = fmaf(a0, hv, acc[0][tt * 4 + m]);
                acc[1][tt * 4 + m] = fmaf(a1, hv, acc[1][tt * 4 + m]);
            }
        }
    }

    #pragma unroll
    for (int si = 0; si < 2; si++) {
        int row = b * kN + s0 + 2 * w + si;
        float m = -3.4e38f;
        #pragma unroll
        for (int j = 0; j < 16; j++) m = fmaxf(m, acc[si][j]);
        #pragma unroll
        for (int o = 16; o > 0; o >>= 1) m = fmaxf(m, __shfl_xor_sync(0xffffffffu, m, o));
        float s = 0.f;
        float e[16];
        #pragma unroll
        for (int j = 0; j < 16; j++) { e[j] = __expf(acc[si][j] - m); s += e[j]; }
        #pragma unroll
        for (int o = 16; o > 0; o >>= 1) s += __shfl_xor_sync(0xffffffffu, s, o);
        float inv = 1.f / s;
        float* sh = shat + (size_t)row * kN;
        float* sn = snorm + (size_t)row * kN;
        #pragma unroll
        for (int j = 0; j < 16; j++) {
            int t = (j >> 2) * 128 + 32 * (j & 3) + lane;
            sh[t] = acc[si][j];
            sn[t] = e[j] * inv;
        }
    }
}

// ---------------------------------------------------------------------------
// K5/K6: ONE persistent kernel per consensus step, grid 256, block 256:
//   A: zero agg32_t + rt = S^T @ r_s  (16-t tiles, 1t x 2r / thread) | bar
//   B: t-graph raw-r scatter (8 iters)                              | bar
//   C: psi2(rt, agg) -> btbuf (16 rows/block, warp = 2 rows)        | bar
//   D: mlp + S_hat add + softmax (16 s-rows/block)
// ---------------------------------------------------------------------------
__global__ __launch_bounds__(256) void step_kernel(
    const float* __restrict__ S, const float* __restrict__ rs,
    const int* __restrict__ eit, const float* __restrict__ eat,
    float* __restrict__ agg, float* __restrict__ rtbuf,
    const float* __restrict__ W2_root, const float* __restrict__ W2_nbr,
    const float* __restrict__ b2, const float* __restrict__ Wm1,
    float* __restrict__ btbuf,
    const float* __restrict__ shat_in, const float* __restrict__ a_s,
    const float* __restrict__ Wm2, const float* __restrict__ bm2,
    float* __restrict__ shat_out, float* __restrict__ snorm_out, int writeShat)
{
    __shared__ union { RtSm a; Psi2Sm c; MlpSm d; } sm;

    int tid = threadIdx.x;
    int bk = blockIdx.x;
    int b  = bk >> 5;
    int tile = bk & 31;

    // ---- phase A: zero agg (blocks 0..127) + rt GEMM (16-t tile) ----
    {
        int gid = bk * 256 + tid;
        if (gid < 32768)
            reinterpret_cast<float4*>(agg)[gid] = make_float4(0.f, 0.f, 0.f, 0.f);
    }
    {
        int t0 = tile * 16;
        const float* Sb = S + (size_t)b * kN * kN;
        const float* Rb = rs + (size_t)b * kN * kR;
        int t_ = tid & 15, rp = tid >> 4;   // t index, r-pair index

        float acc0 = 0.f, acc1 = 0.f;
        for (int ks = 0; ks < 8; ks++) {
            __syncthreads();
            for (int i = tid; i < 1024; i += 256) {
                int sr = i >> 4, c = i & 15;
                sm.a.Ssm[sr][c] = Sb[(size_t)(ks * 64 + sr) * kN + t0 + c];
            }
            for (int i = tid; i < 2048; i += 256) {
                int sr = i >> 5, c = i & 31;
                sm.a.Rsm[sr][c] = Rb[(size_t)(ks * 64 + sr) * kR + c];
            }
            __syncthreads();
            #pragma unroll 8
            for (int k = 0; k < 64; k++) {
                float sv = sm.a.Ssm[k][t_];
                float2 rv = *reinterpret_cast<const float2*>(&sm.a.Rsm[k][2 * rp]);
                acc0 = fmaf(sv, rv.x, acc0);
                acc1 = fmaf(sv, rv.y, acc1);
            }
        }
        float* rt0 = rtbuf + ((size_t)b * kN + t0 + t_) * kR + 2 * rp;
        *reinterpret_cast<float2*>(rt0) = make_float2(acc0, acc1);
    }

    grid_bar(256);

    // ---- phase B: scatter rt over t-graph edges (524288 tasks / 65536 thr) ----
    for (int it = 0; it < 8; it++) {
        int gid = it * 65536 + bk * 256 + tid;
        int e = gid >> 3, c = gid & 7;
        int s = eit[e], d = eit[kE + e];
        float w = eat[e];
        float4 v = *reinterpret_cast<const float4*>(rtbuf + (size_t)s * 32 + c * 4);
        float* p = agg + (size_t)d * 32 + c * 4;
        asm volatile("red.global.add.v4.f32 [%0], {%1,%2,%3,%4};"
                     :: "l"(p), "f"(v.x * w), "f"(v.y * w), "f"(v.z * w), "f"(v.w * w)
                     : "memory");
    }

    grid_bar(256);

    // ---- phase C: psi2 -> btbuf (16 rows/block) ----
    psi2_body<2>(sm.c, bk * 16, rtbuf, agg, W2_root, W2_nbr, b2, Wm1,
                 nullptr, btbuf, 0);

    grid_bar(256);

    // ---- phase D: mlp + softmax, 16 s-rows ----
    mlp_softmax_body(sm.d, b, tile * 16, shat_in, a_s, btbuf,
                     Wm2, bm2[0], shat_out, snorm_out, writeShat);
}

// ---------------------------------------------------------------------------
// Host launch (6 kernels)
// ---------------------------------------------------------------------------
extern "C" void kernel_launch(void* const* d_in, const int* in_sizes, int n_in,
                              void* d_out, int out_size)
{
    (void)in_sizes; (void)n_in; (void)out_size;
    const float* x_s     = (const float*)d_in[0];
    const int*   ei_s    = (const int*)  d_in[1];
    const float* ea_s    = (const float*)d_in[2];
    const float* x_t     = (const float*)d_in[4];
    const int*   ei_t    = (const int*)  d_in[5];
    const float* ea_t    = (const float*)d_in[6];
    const float* r_all   = (const float*)d_in[8];
    const float* W1_root = (const float*)d_in[9];
    const float* W1_nbr  = (const float*)d_in[10];
    const float* b1      = (const float*)d_in[11];
    const float* W2_root = (const float*)d_in[12];
    const float* W2_nbr  = (const float*)d_in[13];
    const float* b2      = (const float*)d_in[14];
    const float* Wm1     = (const float*)d_in[15];
    const float* bm1     = (const float*)d_in[16];
    const float* Wm2     = (const float*)d_in[17];
    const float* bm2     = (const float*)d_in[18];

    float* outS0 = (float*)d_out;
    float* outSL = outS0 + SZ_S;

    float* sc = nullptr;
    cudaGetSymbolAddress((void**)&sc, g_scratch);
    float* agg64s = sc + OFF_AGG64S;
    float* agg64t = sc + OFF_AGG64T;
    float* agg32s = sc + OFF_AGG32S;
    float* agg32t = sc + OFF_AGG32T;
    float* ys     = sc + OFF_YS;
    float* yt     = sc + OFF_YT;
    float* hs     = sc + OFF_HS;
    float* ht     = sc + OFF_HT;
    float* Shat   = sc + OFF_SHAT;
    float* Snorm  = sc + OFF_SNORM;
    float* rtbuf  = sc + OFF_RT;
    float* asbuf  = sc + OFF_AS;
    float* btbuf  = sc + OFF_BT;

    // K1: projection (both graphs) + zero atomic buffers
    proj_zero_kernel<<<dim3(256, 5), 256>>>(x_s, x_t, W1_nbr, ys, yt, sc + OFF_AGG64S);

    // K2: all input-side scatters
    scatter_all<<<dim3(4096, 4), 256>>>(ys, yt, r_all, ei_s, ei_t, ea_s, ea_t,
                                        agg64s, agg64t, agg32s);

    // K3: root GEMM (-> hs, ht) + a_s precompute (both steps)
    root_psi2_kernel<<<768, 256>>>(x_s, x_t, W1_root, b1, agg64s, agg64t, hs, ht,
                                   r_all, agg32s, W2_root, W2_nbr, b2, Wm1, bm1, asbuf);

    // K4: S_hat0 GEMM + softmax -> Shat, outS0
    gemm_softmax_kernel<<<256, 256>>>(hs, ht, Shat, outS0);

    // K5: consensus step 0 (fused chain)
    step_kernel<<<256, 256>>>(outS0, r_all, ei_t, ea_t, agg32t, rtbuf,
                              W2_root, W2_nbr, b2, Wm1, btbuf,
                              Shat, asbuf, Wm2, bm2, Shat, Snorm, 1);

    // K6: consensus step 1 (fused chain)
    step_kernel<<<256, 256>>>(Snorm, r_all + SZ_NTR, ei_t, ea_t, agg32t, rtbuf,
                              W2_root, W2_nbr, b2, Wm1, btbuf,
                              Shat, asbuf + SZ_NTR, Wm2, bm2, nullptr, outSL, 0);
}

// round 6
// speedup vs baseline: 1.5609x; 1.0423x over previous
#include <cuda_runtime.h>
#include <cstdint>

// ---------------------------------------------------------------------------
// Problem constants
// ---------------------------------------------------------------------------
constexpr int kB   = 8;
constexpr int kN   = 512;
constexpr int kE   = 65536;
constexpr int kNT  = kB * kN;      // 4096
constexpr int kDH  = 64;
constexpr int kR   = 32;

constexpr size_t SZ_NTDH = (size_t)kNT * kDH;     // 262144
constexpr size_t SZ_NTR  = (size_t)kNT * kR;      // 131072
constexpr size_t SZ_S    = (size_t)kB * kN * kN;  // 2097152

constexpr size_t OFF_AGG64S = 0;
constexpr size_t OFF_AGG64T = OFF_AGG64S + SZ_NTDH;
constexpr size_t OFF_AGG32S = OFF_AGG64T + SZ_NTDH;   // 2 slots (steps 0,1)
constexpr size_t OFF_AGG32T = OFF_AGG32S + 2 * SZ_NTR;
constexpr size_t OFF_YS     = OFF_AGG32T + SZ_NTR;
constexpr size_t OFF_YT     = OFF_YS     + SZ_NTDH;
constexpr size_t OFF_HS     = OFF_YT     + SZ_NTDH;
constexpr size_t OFF_HT     = OFF_HS     + SZ_NTDH;
constexpr size_t OFF_SHAT   = OFF_HT     + SZ_NTDH;
constexpr size_t OFF_SNORM  = OFF_SHAT   + SZ_S;
constexpr size_t OFF_RT     = OFF_SNORM  + SZ_S;
constexpr size_t OFF_AS     = OFF_RT     + SZ_NTR;    // 2 steps
constexpr size_t OFF_BT     = OFF_AS     + 2 * SZ_NTR;
constexpr size_t SCRATCH_TOTAL = OFF_BT + SZ_NTR;

__device__ float g_scratch[SCRATCH_TOTAL];

constexpr int NBLK = 256;

// Ticket grid barrier (monotonic counter: safe across graph replays)
__device__ unsigned int g_bar = 0;

__device__ __forceinline__ void grid_bar() {
    __syncthreads();
    __threadfence();
    if (threadIdx.x == 0) {
        unsigned old = atomicAdd(&g_bar, 1u);
        unsigned target = (old / NBLK + 1u) * NBLK;
        while (*(volatile unsigned*)&g_bar < target) { }
    }
    __syncthreads();
    __threadfence();
}

__device__ __forceinline__ void red4(float* p, float4 v, float w) {
    asm volatile("red.global.add.v4.f32 [%0], {%1,%2,%3,%4};"
                 :: "l"(p), "f"(v.x * w), "f"(v.y * w), "f"(v.z * w), "f"(v.w * w)
                 : "memory");
}

__device__ __forceinline__ float dot4(float4 a, float4 b, float acc) {
    return fmaf(a.x, b.x, fmaf(a.y, b.y, fmaf(a.z, b.z, fmaf(a.w, b.w, acc))));
}

// ---------------------------------------------------------------------------
// Shared memory layouts (union; all member sizes multiple of 16B)
// ---------------------------------------------------------------------------
struct RootSm { float As[16][128]; };                         // 8 KB
struct Psi2Sm {                                               // ~25 KB
    float rsm[8][4][33];
    float gsm[8][4][33];
    float osm[8][4][33];
    float wr[32 * 33];
    float wn[32 * 33];
    float wm[32 * 33];
};
struct GemmSm { float hsS[16][68]; float htS[128][68]; };     // 38.3 KB
struct RtSm   { float St[16][68];  float Rt[32][68]; };       // 12.8 KB
struct MlpSm  { float Bsm[128][36]; float Asm[16][36]; float w2[32]; }; // 20.4 KB

union MegaSm {
    RootSm r; Psi2Sm p; GemmSm g; RtSm a; MlpSm d;
};

// ---------------------------------------------------------------------------
// psi_2 + Wm1 body (weights + operands staged in smem; scalar, small phase):
//   o = relu( r @ W2_root + agg @ W2_nbr + b2 ); out = o @ Wm1 (+ bm1)
// Covers 8 warps * RPW rows starting at row_base.
// ---------------------------------------------------------------------------
template<int RPW>
__device__ __forceinline__ void psi2_body(
    Psi2Sm& sm, int row_base,
    const float* __restrict__ r, const float* __restrict__ agg,
    const float* __restrict__ W2_root, const float* __restrict__ W2_nbr,
    const float* __restrict__ b2, const float* __restrict__ Wm1,
    const float* __restrict__ bm1, float* __restrict__ out, int hasBm1)
{
    int tid = threadIdx.x;
    for (int i = tid; i < 1024; i += 256) {
        int k = i >> 5, c = i & 31;
        sm.wr[k * 33 + c] = W2_root[i];
        sm.wn[k * 33 + c] = W2_nbr[i];
        sm.wm[k * 33 + c] = Wm1[i];
    }
    int warp = tid >> 5, lane = tid & 31;
    int row0 = row_base + warp * RPW;

    #pragma unroll
    for (int rr = 0; rr < RPW; rr++) {
        sm.rsm[warp][rr][lane] = r[(size_t)(row0 + rr) * 32 + lane];
        sm.gsm[warp][rr][lane] = agg[(size_t)(row0 + rr) * 32 + lane];
    }
    __syncthreads();

    float o[RPW];
    float bv = b2[lane];
    #pragma unroll
    for (int rr = 0; rr < RPW; rr++) o[rr] = bv;
    #pragma unroll 8
    for (int k = 0; k < 32; k++) {
        float wr = sm.wr[k * 33 + lane];
        float wn = sm.wn[k * 33 + lane];
        #pragma unroll
        for (int rr = 0; rr < RPW; rr++) {
            o[rr] = fmaf(sm.rsm[warp][rr][k], wr, o[rr]);
            o[rr] = fmaf(sm.gsm[warp][rr][k], wn, o[rr]);
        }
    }
    #pragma unroll
    for (int rr = 0; rr < RPW; rr++) sm.osm[warp][rr][lane] = fmaxf(o[rr], 0.f);
    __syncwarp();

    float a[RPW];
    float b0 = hasBm1 ? bm1[lane] : 0.f;
    #pragma unroll
    for (int rr = 0; rr < RPW; rr++) a[rr] = b0;
    #pragma unroll 8
    for (int k = 0; k < 32; k++) {
        float w = sm.wm[k * 33 + lane];
        #pragma unroll
        for (int rr = 0; rr < RPW; rr++) a[rr] = fmaf(sm.osm[warp][rr][k], w, a[rr]);
    }
    #pragma unroll
    for (int rr = 0; rr < RPW; rr++) out[(size_t)(row0 + rr) * 32 + lane] = a[rr];
}

// ---------------------------------------------------------------------------
// proj/root GEMM tile: 16 rows x 64 cols, K=128, float4 A reads.
// ---------------------------------------------------------------------------
template<bool RELU, bool HASBIAS, bool HASADD>
__device__ __forceinline__ void rowgemm_tile(
    RootSm& sm, int row0,
    const float* __restrict__ A, const float* __restrict__ W,
    const float* __restrict__ bias, const float* __restrict__ add,
    float* __restrict__ out)
{
    int tid = threadIdx.x;
    const float4* A4 = reinterpret_cast<const float4*>(A + (size_t)row0 * 128);
    __syncthreads();
    for (int i = tid; i < 512; i += 256)
        *reinterpret_cast<float4*>(&sm.As[i >> 5][(i & 31) * 4]) = A4[i];
    __syncthreads();

    int j = tid & 63, g = tid >> 6;
    float acc[4];
    float bv = HASBIAS ? bias[j] : 0.f;
    #pragma unroll
    for (int rr = 0; rr < 4; rr++) acc[rr] = bv;

    #pragma unroll 4
    for (int k4 = 0; k4 < 32; k4++) {
        float w0 = __ldg(&W[(k4 * 4 + 0) * 64 + j]);
        float w1 = __ldg(&W[(k4 * 4 + 1) * 64 + j]);
        float w2 = __ldg(&W[(k4 * 4 + 2) * 64 + j]);
        float w3 = __ldg(&W[(k4 * 4 + 3) * 64 + j]);
        #pragma unroll
        for (int rr = 0; rr < 4; rr++) {
            float4 av = *reinterpret_cast<const float4*>(&sm.As[g * 4 + rr][k4 * 4]);
            acc[rr] = fmaf(av.x, w0, fmaf(av.y, w1, fmaf(av.z, w2, fmaf(av.w, w3, acc[rr]))));
        }
    }
    #pragma unroll
    for (int rr = 0; rr < 4; rr++) {
        size_t idx = (size_t)(row0 + g * 4 + rr) * 64 + j;
        float v = acc[rr];
        if (HASADD) v += add[idx];
        if (RELU)   v = fmaxf(v, 0.f);
        out[idx] = v;
    }
}

// ---------------------------------------------------------------------------
// mlp + softmax body: 16 s-rows, warp = 2 rows, float4 over r.
// ---------------------------------------------------------------------------
__device__ __forceinline__ void mlp_softmax_body(
    MlpSm& sm, int b, int s0,
    const float* __restrict__ shat_in,
    const float* __restrict__ a_s, const float* __restrict__ b_t,
    const float* __restrict__ Wm2, float bm2v,
    float* __restrict__ shat_out, float* __restrict__ snorm_out, int writeShat)
{
    int tid = threadIdx.x;
    int w = tid >> 5, lane = tid & 31;

    if (tid < 32) sm.w2[tid] = Wm2[tid];
    const float4* Ab4 = reinterpret_cast<const float4*>(a_s + ((size_t)b * kN + s0) * kR);
    for (int i = tid; i < 128; i += 256)
        *reinterpret_cast<float4*>(&sm.Asm[i >> 3][(i & 7) * 4]) = Ab4[i];

    float acc[2][16];
    #pragma unroll
    for (int i = 0; i < 2; i++)
        #pragma unroll
        for (int j = 0; j < 16; j++) acc[i][j] = 0.f;

    for (int tt = 0; tt < 4; tt++) {
        __syncthreads();
        const float4* Bb4 = reinterpret_cast<const float4*>(b_t + ((size_t)b * kN + tt * 128) * kR);
        for (int i = tid; i < 1024; i += 256)
            *reinterpret_cast<float4*>(&sm.Bsm[i >> 3][(i & 7) * 4]) = Bb4[i];
        __syncthreads();

        #pragma unroll
        for (int r4 = 0; r4 < 8; r4++) {
            float4 ww = *reinterpret_cast<const float4*>(&sm.w2[r4 * 4]);
            float4 a0 = *reinterpret_cast<const float4*>(&sm.Asm[2 * w][r4 * 4]);
            float4 a1 = *reinterpret_cast<const float4*>(&sm.Asm[2 * w + 1][r4 * 4]);
            #pragma unroll
            for (int m = 0; m < 4; m++) {
                float4 bv = *reinterpret_cast<const float4*>(&sm.Bsm[lane + 32 * m][r4 * 4]);
                int j = tt * 4 + m;
                float d;
                d = fmaxf(a0.x - bv.x, 0.f); acc[0][j] = fmaf(d, ww.x, acc[0][j]);
                d = fmaxf(a0.y - bv.y, 0.f); acc[0][j] = fmaf(d, ww.y, acc[0][j]);
                d = fmaxf(a0.z - bv.z, 0.f); acc[0][j] = fmaf(d, ww.z, acc[0][j]);
                d = fmaxf(a0.w - bv.w, 0.f); acc[0][j] = fmaf(d, ww.w, acc[0][j]);
                d = fmaxf(a1.x - bv.x, 0.f); acc[1][j] = fmaf(d, ww.x, acc[1][j]);
                d = fmaxf(a1.y - bv.y, 0.f); acc[1][j] = fmaf(d, ww.y, acc[1][j]);
                d = fmaxf(a1.z - bv.z, 0.f); acc[1][j] = fmaf(d, ww.z, acc[1][j]);
                d = fmaxf(a1.w - bv.w, 0.f); acc[1][j] = fmaf(d, ww.w, acc[1][j]);
            }
        }
    }

    #pragma unroll
    for (int si = 0; si < 2; si++) {
        int row = b * kN + s0 + 2 * w + si;
        const float* shi = shat_in + (size_t)row * kN;
        float v[16];
        #pragma unroll
        for (int j = 0; j < 16; j++) {
            int t = (j >> 2) * 128 + 32 * (j & 3) + lane;
            v[j] = shi[t] + acc[si][j] + bm2v;
        }
        float m = -3.4e38f;
        #pragma unroll
        for (int j = 0; j < 16; j++) m = fmaxf(m, v[j]);
        #pragma unroll
        for (int o = 16; o > 0; o >>= 1) m = fmaxf(m, __shfl_xor_sync(0xffffffffu, m, o));
        float s = 0.f;
        float e[16];
        #pragma unroll
        for (int j = 0; j < 16; j++) { e[j] = __expf(v[j] - m); s += e[j]; }
        #pragma unroll
        for (int o = 16; o > 0; o >>= 1) s += __shfl_xor_sync(0xffffffffu, s, o);
        float inv = 1.f / s;
        float* sn = snorm_out + (size_t)row * kN;
        #pragma unroll
        for (int j = 0; j < 16; j++) {
            int t = (j >> 2) * 128 + 32 * (j & 3) + lane;
            sn[t] = e[j] * inv;
        }
        if (writeShat) {
            float* sh = shat_out + (size_t)row * kN;
            #pragma unroll
            for (int j = 0; j < 16; j++) {
                int t = (j >> 2) * 128 + 32 * (j & 3) + lane;
                sh[t] = v[j];
            }
        }
    }
}

// ---------------------------------------------------------------------------
// THE kernel: all 12 phases, 11 grid barriers, 256 blocks x 256 threads.
// __launch_bounds__(256, 2) guarantees >=2 blocks/SM => 256 co-resident.
// ---------------------------------------------------------------------------
__global__ __launch_bounds__(256, 2) void mega_kernel(
    const float* __restrict__ x_s, const float* __restrict__ x_t,
    const int* __restrict__ eis, const float* __restrict__ eas,
    const int* __restrict__ eit, const float* __restrict__ eat,
    const float* __restrict__ r_all,
    const float* __restrict__ W1_root, const float* __restrict__ W1_nbr,
    const float* __restrict__ b1,
    const float* __restrict__ W2_root, const float* __restrict__ W2_nbr,
    const float* __restrict__ b2,
    const float* __restrict__ Wm1, const float* __restrict__ bm1,
    const float* __restrict__ Wm2, const float* __restrict__ bm2,
    float* __restrict__ outS0, float* __restrict__ outSL)
{
    __shared__ MegaSm sm;

    int tid = threadIdx.x;
    int bk = blockIdx.x;
    int w = tid >> 5, lane = tid & 31;

    float* agg64s = g_scratch + OFF_AGG64S;
    float* agg64t = g_scratch + OFF_AGG64T;
    float* agg32s = g_scratch + OFF_AGG32S;
    float* agg32t = g_scratch + OFF_AGG32T;
    float* ys     = g_scratch + OFF_YS;
    float* yt     = g_scratch + OFF_YT;
    float* hs     = g_scratch + OFF_HS;
    float* ht     = g_scratch + OFF_HT;
    float* Shat   = g_scratch + OFF_SHAT;
    float* Snorm  = g_scratch + OFF_SNORM;
    float* rtbuf  = g_scratch + OFF_RT;
    float* asbuf  = g_scratch + OFF_AS;
    float* btbuf  = g_scratch + OFF_BT;

    // ======== P0: zero atomic buffers + projection y = x @ W1_nbr ========
    {
        float4* z4 = reinterpret_cast<float4*>(agg64s);
        int base = bk * 256 + tid;
        float4 zz = make_float4(0.f, 0.f, 0.f, 0.f);
        z4[base] = zz; z4[base + 65536] = zz; z4[base + 131072] = zz;
    }
    #pragma unroll 1
    for (int it = 0; it < 2; it++) {
        int tl = bk + 256 * it;
        int y = tl >> 8;
        rowgemm_tile<false, false, false>(sm.r, (tl & 255) * 16,
                                          y ? x_t : x_s, W1_nbr, nullptr, nullptr,
                                          y ? yt : ys);
    }
    grid_bar();

    // ======== P1: all input-side scatters (atomics) ========
    #pragma unroll 1
    for (int graph = 0; graph < 2; graph++) {
        const float* yy  = graph ? yt : ys;
        const int*   ei  = graph ? eit : eis;
        const float* ea  = graph ? eat : eas;
        float*       agg = graph ? agg64t : agg64s;
        #pragma unroll 2
        for (int it = 0; it < 16; it++) {
            int gid = it * 65536 + bk * 256 + tid;
            int e = gid >> 4, c = gid & 15;
            int s = ei[e], d = ei[kE + e];
            float wgt = ea[e];
            float4 v = *reinterpret_cast<const float4*>(yy + (size_t)s * 64 + c * 4);
            red4(agg + (size_t)d * 64 + c * 4, v, wgt);
        }
    }
    #pragma unroll 1
    for (int step = 0; step < 2; step++) {
        const float* yy  = r_all  + (size_t)step * SZ_NTR;
        float*       agg = agg32s + (size_t)step * SZ_NTR;
        #pragma unroll 2
        for (int it = 0; it < 8; it++) {
            int gid = it * 65536 + bk * 256 + tid;
            int e = gid >> 3, c = gid & 7;
            int s = eis[e], d = eis[kE + e];
            float wgt = eas[e];
            float4 v = *reinterpret_cast<const float4*>(yy + (size_t)s * 32 + c * 4);
            red4(agg + (size_t)d * 32 + c * 4, v, wgt);
        }
    }
    grid_bar();

    // ======== P2: root GEMM (h = relu(x@W1_root + b1 + agg)) + a_s psi2 ====
    #pragma unroll 1
    for (int it = 0; it < 2; it++) {
        int tl = bk + 256 * it;
        int y = tl >> 8;
        rowgemm_tile<true, true, true>(sm.r, (tl & 255) * 16,
                                       y ? x_t : x_s, W1_root, b1,
                                       y ? agg64t : agg64s,
                                       y ? ht : hs);
    }
    __syncthreads();
    {
        int step = bk >> 7;
        psi2_body<4>(sm.p, (bk & 127) * 32,
                     r_all + (size_t)step * SZ_NTR, agg32s + (size_t)step * SZ_NTR,
                     W2_root, W2_nbr, b2, Wm1, bm1,
                     asbuf + (size_t)step * SZ_NTR, 1);
    }
    grid_bar();

    // ======== P3: S_hat0 = h_s @ h_t^T + row softmax ========
    {
        int b  = bk >> 5;
        int s0 = (bk & 31) * 16;

        const float4* hsb4 = reinterpret_cast<const float4*>(hs + ((size_t)b * kN + s0) * kDH);
        for (int i = tid; i < 256; i += 256)
            *reinterpret_cast<float4*>(&sm.g.hsS[i >> 4][(i & 15) * 4]) = hsb4[i];

        float acc[2][16];
        #pragma unroll
        for (int i = 0; i < 2; i++)
            #pragma unroll
            for (int j = 0; j < 16; j++) acc[i][j] = 0.f;

        for (int tt = 0; tt < 4; tt++) {
            __syncthreads();
            const float4* htb4 = reinterpret_cast<const float4*>(ht + ((size_t)b * kN + tt * 128) * kDH);
            for (int i = tid; i < 2048; i += 256)
                *reinterpret_cast<float4*>(&sm.g.htS[i >> 4][(i & 15) * 4]) = htb4[i];
            __syncthreads();

            #pragma unroll 4
            for (int k4 = 0; k4 < 16; k4++) {
                float4 a0 = *reinterpret_cast<const float4*>(&sm.g.hsS[2 * w][k4 * 4]);
                float4 a1 = *reinterpret_cast<const float4*>(&sm.g.hsS[2 * w + 1][k4 * 4]);
                #pragma unroll
                for (int m = 0; m < 4; m++) {
                    float4 hv = *reinterpret_cast<const float4*>(&sm.g.htS[lane + 32 * m][k4 * 4]);
                    acc[0][tt * 4 + m] = dot4(a0, hv, acc[0][tt * 4 + m]);
                    acc[1][tt * 4 + m] = dot4(a1, hv, acc[1][tt * 4 + m]);
                }
            }
        }

        #pragma unroll
        for (int si = 0; si < 2; si++) {
            int row = b * kN + s0 + 2 * w + si;
            float m = -3.4e38f;
            #pragma unroll
            for (int j = 0; j < 16; j++) m = fmaxf(m, acc[si][j]);
            #pragma unroll
            for (int o = 16; o > 0; o >>= 1) m = fmaxf(m, __shfl_xor_sync(0xffffffffu, m, o));
            float s = 0.f;
            float e[16];
            #pragma unroll
            for (int j = 0; j < 16; j++) { e[j] = __expf(acc[si][j] - m); s += e[j]; }
            #pragma unroll
            for (int o = 16; o > 0; o >>= 1) s += __shfl_xor_sync(0xffffffffu, s, o);
            float inv = 1.f / s;
            float* sh = Shat + (size_t)row * kN;
            float* sn = outS0 + (size_t)row * kN;
            #pragma unroll
            for (int j = 0; j < 16; j++) {
                int t = (j >> 2) * 128 + 32 * (j & 3) + lane;
                sh[t] = acc[si][j];
                sn[t] = e[j] * inv;
            }
        }
    }
    grid_bar();

    // ======== consensus steps ========
    #pragma unroll 1
    for (int step = 0; step < 2; step++) {
        const float* Ssrc = step ? Snorm : outS0;
        const float* rsk  = r_all + (size_t)step * SZ_NTR;
        const float* ask  = asbuf + (size_t)step * SZ_NTR;
        float* snorm_out  = step ? outSL : Snorm;
        int writeShat = (step == 0);

        // ---- A: zero agg32t + rt = S^T @ r_s (transposed staging, float4) ----
        {
            int gid = bk * 256 + tid;
            if (gid < 32768)
                reinterpret_cast<float4*>(agg32t)[gid] = make_float4(0.f, 0.f, 0.f, 0.f);
        }
        {
            int b = bk >> 5;
            int t0 = (bk & 31) * 16;
            const float* Sb = Ssrc + (size_t)b * kN * kN;
            const float* Rb = rsk + (size_t)b * kN * kR;
            int t_ = tid & 15, rp = tid >> 4;

            float acc0 = 0.f, acc1 = 0.f;
            for (int ks = 0; ks < 8; ks++) {
                __syncthreads();
                {   // transpose-stage S chunk: St[t][s]
                    int s = tid >> 2, t4 = tid & 3;
                    float4 v = *reinterpret_cast<const float4*>(
                        &Sb[(size_t)(ks * 64 + s) * kN + t0 + t4 * 4]);
                    sm.a.St[t4 * 4 + 0][s] = v.x;
                    sm.a.St[t4 * 4 + 1][s] = v.y;
                    sm.a.St[t4 * 4 + 2][s] = v.z;
                    sm.a.St[t4 * 4 + 3][s] = v.w;
                }
                #pragma unroll
                for (int i = tid; i < 512; i += 256) {  // transpose-stage r: Rt[r][s]
                    int s = i >> 3, r4 = i & 7;
                    float4 v = *reinterpret_cast<const float4*>(
                        &Rb[(size_t)(ks * 64 + s) * kR + r4 * 4]);
                    sm.a.Rt[r4 * 4 + 0][s] = v.x;
                    sm.a.Rt[r4 * 4 + 1][s] = v.y;
                    sm.a.Rt[r4 * 4 + 2][s] = v.z;
                    sm.a.Rt[r4 * 4 + 3][s] = v.w;
                }
                __syncthreads();
                #pragma unroll 4
                for (int k4 = 0; k4 < 16; k4++) {
                    float4 sv = *reinterpret_cast<const float4*>(&sm.a.St[t_][k4 * 4]);
                    float4 ra = *reinterpret_cast<const float4*>(&sm.a.Rt[2 * rp][k4 * 4]);
                    float4 rb = *reinterpret_cast<const float4*>(&sm.a.Rt[2 * rp + 1][k4 * 4]);
                    acc0 = dot4(sv, ra, acc0);
                    acc1 = dot4(sv, rb, acc1);
                }
            }
            float* rt0 = rtbuf + ((size_t)b * kN + t0 + t_) * kR + 2 * rp;
            *reinterpret_cast<float2*>(rt0) = make_float2(acc0, acc1);
        }
        grid_bar();

        // ---- B: scatter rt over t-graph edges ----
        #pragma unroll 2
        for (int it = 0; it < 8; it++) {
            int gid = it * 65536 + bk * 256 + tid;
            int e = gid >> 3, c = gid & 7;
            int s = eit[e], d = eit[kE + e];
            float wgt = eat[e];
            float4 v = *reinterpret_cast<const float4*>(rtbuf + (size_t)s * 32 + c * 4);
            red4(agg32t + (size_t)d * 32 + c * 4, v, wgt);
        }
        grid_bar();

        // ---- C: psi2(rt, agg) @ Wm1 -> btbuf ----
        psi2_body<2>(sm.p, bk * 16, rtbuf, agg32t, W2_root, W2_nbr, b2, Wm1,
                     nullptr, btbuf, 0);
        grid_bar();

        // ---- D: mlp + S_hat add + softmax ----
        mlp_softmax_body(sm.d, bk >> 5, (bk & 31) * 16, Shat, ask, btbuf,
                         Wm2, bm2[0], Shat, snorm_out, writeShat);
        if (step == 0) grid_bar();
    }
}

// ---------------------------------------------------------------------------
// Host launch (ONE kernel)
// ---------------------------------------------------------------------------
extern "C" void kernel_launch(void* const* d_in, const int* in_sizes, int n_in,
                              void* d_out, int out_size)
{
    (void)in_sizes; (void)n_in; (void)out_size;
    const float* x_s     = (const float*)d_in[0];
    const int*   ei_s    = (const int*)  d_in[1];
    const float* ea_s    = (const float*)d_in[2];
    const float* x_t     = (const float*)d_in[4];
    const int*   ei_t    = (const int*)  d_in[5];
    const float* ea_t    = (const float*)d_in[6];
    const float* r_all   = (const float*)d_in[8];
    const float* W1_root = (const float*)d_in[9];
    const float* W1_nbr  = (const float*)d_in[10];
    const float* b1      = (const float*)d_in[11];
    const float* W2_root = (const float*)d_in[12];
    const float* W2_nbr  = (const float*)d_in[13];
    const float* b2      = (const float*)d_in[14];
    const float* Wm1     = (const float*)d_in[15];
    const float* bm1     = (const float*)d_in[16];
    const float* Wm2     = (const float*)d_in[17];
    const float* bm2     = (const float*)d_in[18];

    float* outS0 = (float*)d_out;
    float* outSL = outS0 + SZ_S;

    mega_kernel<<<NBLK, 256>>>(x_s, x_t, ei_s, ea_s, ei_t, ea_t, r_all,
                               W1_root, W1_nbr, b1, W2_root, W2_nbr, b2,
                               Wm1, bm1, Wm2, bm2, outS0, outSL);
}